// round 8
// baseline (speedup 1.0000x reference)
#include <cuda_runtime.h>
#include <math.h>
#include <stdint.h>

#define NN 100000
#define NE 1600000
#define FD 128
#define FD4 (FD/4)
#define SCAN_T 1024
#define SCAN_B ((NN + SCAN_T - 1) / SCAN_T)   // 98
#define NTILES ((NN + 63) / 64)               // 1563
#define GRID_P 148                            // persistent blocks (1/SM)

// padded smem strides (floats) for bank-conflict-free MMA fragment loads
#define SA_STR 132   // 64 rows
#define SW_STR 136   // 128 rows
#define SMEM_BYTES ((128*SW_STR + 2*64*SA_STR) * 4)   // 137,216 B

// ---------------- static device scratch ----------------
__device__ float g_h0[(size_t)NN * FD];
__device__ float g_h1[(size_t)NN * FD];
__device__ int   g_cnt_src[NN];
__device__ int   g_cnt_dst[NN];
__device__ float g_norm_src[NN];
__device__ float g_norm_dst[NN];
__device__ int   g_rowstart[NN];
__device__ int   g_fill[NN];
__device__ int   g_bsum[SCAN_B];
__device__ int   g_boff[SCAN_B];
__device__ int   g_csr_src[NE];

// ---------------- setup kernels ----------------
__global__ void zero_counts_kernel() {
    int i = blockIdx.x * blockDim.x + threadIdx.x;
    if (i < NN) { g_cnt_src[i] = 0; g_cnt_dst[i] = 0; }
}

__global__ void count_deg_kernel(const int* __restrict__ src,
                                 const int* __restrict__ dst) {
    int i = blockIdx.x * blockDim.x + threadIdx.x;
    if (i < NE) {
        atomicAdd(&g_cnt_src[src[i]], 1);
        atomicAdd(&g_cnt_dst[dst[i]], 1);
    }
}

__global__ void make_norm_kernel() {
    int i = blockIdx.x * blockDim.x + threadIdx.x;
    if (i < NN) {
        g_norm_src[i] = rsqrtf(fmaxf((float)g_cnt_src[i], 1.0f));
        g_norm_dst[i] = rsqrtf(fmaxf((float)g_cnt_dst[i], 1.0f));
    }
}

__global__ void __launch_bounds__(SCAN_T) scan_block_kernel() {
    __shared__ int s[SCAN_T];
    int t = threadIdx.x;
    int i = blockIdx.x * SCAN_T + t;
    int v = (i < NN) ? g_cnt_dst[i] : 0;
    s[t] = v;
    __syncthreads();
    #pragma unroll
    for (int off = 1; off < SCAN_T; off <<= 1) {
        int x = (t >= off) ? s[t - off] : 0;
        __syncthreads();
        s[t] += x;
        __syncthreads();
    }
    if (i < NN) g_rowstart[i] = s[t] - v;
    if (t == SCAN_T - 1) g_bsum[blockIdx.x] = s[t];
}

__global__ void scan_bsums_kernel() {
    __shared__ int s[128];
    int t = threadIdx.x;
    int v = (t < SCAN_B) ? g_bsum[t] : 0;
    s[t] = v;
    __syncthreads();
    #pragma unroll
    for (int off = 1; off < 128; off <<= 1) {
        int x = (t >= off) ? s[t - off] : 0;
        __syncthreads();
        s[t] += x;
        __syncthreads();
    }
    if (t < SCAN_B) g_boff[t] = s[t] - v;
}

__global__ void add_offsets_kernel() {
    int i = blockIdx.x * blockDim.x + threadIdx.x;
    if (i < NN) {
        int v = g_rowstart[i] + g_boff[i >> 10];
        g_rowstart[i] = v;
        g_fill[i] = v;
    }
}

__global__ void fill_csr_kernel(const int* __restrict__ src,
                                const int* __restrict__ dst) {
    int e = blockIdx.x * blockDim.x + threadIdx.x;
    if (e < NE) {
        int pos = atomicAdd(&g_fill[dst[e]], 1);
        g_csr_src[pos] = src[e];
    }
}

// ---------------- tf32 helpers ----------------
__device__ __forceinline__ void f2tf32_split(float a, uint32_t& hi, uint32_t& lo) {
    asm("cvt.rna.tf32.f32 %0, %1;" : "=r"(hi) : "f"(a));
    float r = a - __uint_as_float(hi);
    asm("cvt.rna.tf32.f32 %0, %1;" : "=r"(lo) : "f"(r));
}

__device__ __forceinline__ void mma_tf32(float* c,
    uint32_t a0, uint32_t a1, uint32_t a2, uint32_t a3,
    uint32_t b0, uint32_t b1)
{
    asm volatile(
        "mma.sync.aligned.m16n8k8.row.col.f32.tf32.tf32.f32 "
        "{%0,%1,%2,%3}, {%4,%5,%6,%7}, {%8,%9}, {%0,%1,%2,%3};"
        : "+f"(c[0]), "+f"(c[1]), "+f"(c[2]), "+f"(c[3])
        : "r"(a0), "r"(a1), "r"(a2), "r"(a3), "r"(b0), "r"(b1));
}

__device__ __forceinline__ float gelu_exact(float x) {
    return 0.5f * x * (1.0f + erff(x * 0.7071067811865476f));
}

// ---------------- producer: linear-stream gather of a 64-row tile ----------------
// warp p (0..7) gathers rows [rowbase + p*8, +8) into sAbuf (stride SA_STR).
template <bool SRCNORM>
__device__ __forceinline__ void gather_tile(
    const float4* __restrict__ hp, int rowbase, int warp, int lane,
    float* __restrict__ sAbuf, int (*sBnd)[9])
{
    int r0 = rowbase + warp * 8;
    {
        int myc = 0;
        int rr = r0 + lane;
        if (lane < 8 && rr < NN) myc = __ldg(&g_cnt_dst[rr]);
        int sum = myc;
        #pragma unroll
        for (int off = 1; off < 8; off <<= 1) {
            int t = __shfl_up_sync(0xFFFFFFFFu, sum, off);
            if ((lane & 7) >= off) sum += t;
        }
        int beg = (r0 < NN) ? __ldg(&g_rowstart[r0]) : 0;
        if (lane == 0) sBnd[warp][0] = beg;
        if (lane < 8)  sBnd[warp][lane + 1] = beg + sum;
    }
    __syncwarp();

    int e   = sBnd[warp][0];
    int end = sBnd[warp][8];
    int cur = 0;
    int next = sBnd[warp][1];
    float4 acc = make_float4(0.f, 0.f, 0.f, 0.f);
    float4* sArow = (float4*)sAbuf;   // stride 33 float4

    float4 v[8]; float ns[8];
    bool pro = (e + 8 <= end);
    if (pro) {
        #pragma unroll
        for (int j = 0; j < 8; ++j) {
            int s = __ldg(&g_csr_src[e + j]);
            if (SRCNORM) ns[j] = __ldg(&g_norm_src[s]);
            v[j] = __ldg(&hp[s * 32 + lane]);
        }
    }
    int ecur = e;
    #pragma unroll 1
    for (; ecur + 16 <= end; ecur += 8) {
        float4 w[8]; float ws[8];
        #pragma unroll
        for (int j = 0; j < 8; ++j) {
            int s = __ldg(&g_csr_src[ecur + 8 + j]);
            if (SRCNORM) ws[j] = __ldg(&g_norm_src[s]);
            w[j] = __ldg(&hp[s * 32 + lane]);
        }
        #pragma unroll
        for (int j = 0; j < 8; ++j) {
            int ee = ecur + j;
            while (ee >= next) {                 // warp-uniform
                sArow[(warp * 8 + cur) * 33 + lane] = acc;
                acc = make_float4(0.f, 0.f, 0.f, 0.f);
                ++cur;
                next = sBnd[warp][cur + 1];
            }
            if (SRCNORM) {
                acc.x += v[j].x * ns[j]; acc.y += v[j].y * ns[j];
                acc.z += v[j].z * ns[j]; acc.w += v[j].w * ns[j];
            } else {
                acc.x += v[j].x; acc.y += v[j].y;
                acc.z += v[j].z; acc.w += v[j].w;
            }
        }
        #pragma unroll
        for (int j = 0; j < 8; ++j) { v[j] = w[j]; if (SRCNORM) ns[j] = ws[j]; }
    }
    if (pro) {
        #pragma unroll
        for (int j = 0; j < 8; ++j) {
            int ee = ecur + j;
            while (ee >= next) {
                sArow[(warp * 8 + cur) * 33 + lane] = acc;
                acc = make_float4(0.f, 0.f, 0.f, 0.f);
                ++cur;
                next = sBnd[warp][cur + 1];
            }
            if (SRCNORM) {
                acc.x += v[j].x * ns[j]; acc.y += v[j].y * ns[j];
                acc.z += v[j].z * ns[j]; acc.w += v[j].w * ns[j];
            } else {
                acc.x += v[j].x; acc.y += v[j].y;
                acc.z += v[j].z; acc.w += v[j].w;
            }
        }
        ecur += 8;
    }
    {   // remainder (< 8 edges)
        float4 rv[8]; float rns[8]; int have = end - ecur;
        #pragma unroll
        for (int j = 0; j < 8; ++j) {
            if (j < have) {
                int s = __ldg(&g_csr_src[ecur + j]);
                if (SRCNORM) rns[j] = __ldg(&g_norm_src[s]);
                rv[j] = __ldg(&hp[s * 32 + lane]);
            }
        }
        #pragma unroll
        for (int j = 0; j < 8; ++j) {
            if (j < have) {
                int ee = ecur + j;
                while (ee >= next) {
                    sArow[(warp * 8 + cur) * 33 + lane] = acc;
                    acc = make_float4(0.f, 0.f, 0.f, 0.f);
                    ++cur;
                    next = sBnd[warp][cur + 1];
                }
                if (SRCNORM) {
                    acc.x += rv[j].x * rns[j]; acc.y += rv[j].y * rns[j];
                    acc.z += rv[j].z * rns[j]; acc.w += rv[j].w * rns[j];
                } else {
                    acc.x += rv[j].x; acc.y += rv[j].y;
                    acc.z += rv[j].z; acc.w += rv[j].w;
                }
            }
        }
    }
    #pragma unroll
    for (int rr = 0; rr < 8; ++rr) {
        if (rr >= cur) {
            sArow[(warp * 8 + rr) * 33 + lane] = acc;
            acc = make_float4(0.f, 0.f, 0.f, 0.f);
        }
    }
}

// ---------------- consumer: 3xTF32 GEMM + epilogue for one tile ----------------
template <bool GELU, bool PRESCALE, bool LNORM>
__device__ __forceinline__ void gemm_tile(
    const float* __restrict__ sA, const float* __restrict__ sW,
    int rowbase, int cw, int lane,
    const float* __restrict__ bias, float* __restrict__ out,
    const float* __restrict__ gamma, const float* __restrict__ beta,
    float2 (*sLN)[8])
{
    int g = lane >> 2;
    int t = lane & 3;
    int rtbase = (cw & 3) * 16;
    int chbase = (cw >> 2) * 64;

    float c[8][4];
    #pragma unroll
    for (int n = 0; n < 8; ++n)
        #pragma unroll
        for (int j = 0; j < 4; ++j) c[n][j] = 0.f;

    #pragma unroll 4
    for (int k = 0; k < 16; ++k) {
        int k0 = k * 8;
        float a0f = sA[(rtbase + g)     * SA_STR + k0 + t];
        float a1f = sA[(rtbase + g + 8) * SA_STR + k0 + t];
        float a2f = sA[(rtbase + g)     * SA_STR + k0 + t + 4];
        float a3f = sA[(rtbase + g + 8) * SA_STR + k0 + t + 4];
        uint32_t ah0, al0, ah1, al1, ah2, al2, ah3, al3;
        f2tf32_split(a0f, ah0, al0);
        f2tf32_split(a1f, ah1, al1);
        f2tf32_split(a2f, ah2, al2);
        f2tf32_split(a3f, ah3, al3);

        #pragma unroll
        for (int n = 0; n < 8; ++n) {
            int ncol = chbase + n * 8 + g;
            float b0f = sW[(k0 + t)     * SW_STR + ncol];
            float b1f = sW[(k0 + t + 4) * SW_STR + ncol];
            uint32_t bh0, bl0, bh1, bl1;
            f2tf32_split(b0f, bh0, bl0);
            f2tf32_split(b1f, bh1, bl1);

            mma_tf32(c[n], ah0, ah1, ah2, ah3, bh0, bh1);
            mma_tf32(c[n], ah0, ah1, ah2, ah3, bl0, bl1);
            mma_tf32(c[n], al0, al1, al2, al3, bh0, bh1);
        }
    }

    int row0 = rowbase + rtbase + g;
    int row1 = row0 + 8;
    float nd0 = 0.f, nd1 = 0.f, ns0 = 1.f, ns1 = 1.f;
    if (row0 < NN) { nd0 = __ldg(&g_norm_dst[row0]); if (PRESCALE) ns0 = __ldg(&g_norm_src[row0]); }
    if (row1 < NN) { nd1 = __ldg(&g_norm_dst[row1]); if (PRESCALE) ns1 = __ldg(&g_norm_src[row1]); }

    if (!LNORM) {
        #pragma unroll
        for (int n = 0; n < 8; ++n) {
            int col = chbase + n * 8 + t * 2;
            float2 bv = *(const float2*)(bias + col);
            if (row0 < NN) {
                float ox = c[n][0] * nd0 + bv.x;
                float oy = c[n][1] * nd0 + bv.y;
                if (GELU) { ox = gelu_exact(ox); oy = gelu_exact(oy); }
                if (PRESCALE) { ox *= ns0; oy *= ns0; }
                *(float2*)(out + (size_t)row0 * FD + col) = make_float2(ox, oy);
            }
            if (row1 < NN) {
                float ox = c[n][2] * nd1 + bv.x;
                float oy = c[n][3] * nd1 + bv.y;
                if (GELU) { ox = gelu_exact(ox); oy = gelu_exact(oy); }
                if (PRESCALE) { ox *= ns1; oy *= ns1; }
                *(float2*)(out + (size_t)row1 * FD + col) = make_float2(ox, oy);
            }
        }
    } else {
        float s0 = 0.f, q0 = 0.f, s1 = 0.f, q1 = 0.f;
        #pragma unroll
        for (int n = 0; n < 8; ++n) {
            int col = chbase + n * 8 + t * 2;
            float2 bv = *(const float2*)(bias + col);
            float h00 = c[n][0] * nd0 + bv.x;
            float h01 = c[n][1] * nd0 + bv.y;
            float h10 = c[n][2] * nd1 + bv.x;
            float h11 = c[n][3] * nd1 + bv.y;
            c[n][0] = h00; c[n][1] = h01; c[n][2] = h10; c[n][3] = h11;
            s0 += h00 + h01; q0 += h00 * h00 + h01 * h01;
            s1 += h10 + h11; q1 += h10 * h10 + h11 * h11;
        }
        int slot = (cw >> 2) * 4 + t;
        sLN[rtbase + g][slot]     = make_float2(s0, q0);
        sLN[rtbase + g + 8][slot] = make_float2(s1, q1);
        asm volatile("bar.sync 1, 256;" ::: "memory");   // consumers only
        float ts0 = 0.f, tq0 = 0.f, ts1 = 0.f, tq1 = 0.f;
        #pragma unroll
        for (int k = 0; k < 8; ++k) {
            float2 p0 = sLN[rtbase + g][k];
            float2 p1 = sLN[rtbase + g + 8][k];
            ts0 += p0.x; tq0 += p0.y;
            ts1 += p1.x; tq1 += p1.y;
        }
        float mu0 = ts0 * (1.0f / FD);
        float mu1 = ts1 * (1.0f / FD);
        float inv0 = rsqrtf(fmaxf(tq0 * (1.0f / FD) - mu0 * mu0, 0.f) + 1e-5f);
        float inv1 = rsqrtf(fmaxf(tq1 * (1.0f / FD) - mu1 * mu1, 0.f) + 1e-5f);
        #pragma unroll
        for (int n = 0; n < 8; ++n) {
            int col = chbase + n * 8 + t * 2;
            float2 gv = *(const float2*)(gamma + col);
            float2 bt = *(const float2*)(beta + col);
            if (row0 < NN) {
                float ox = (c[n][0] - mu0) * inv0 * gv.x + bt.x;
                float oy = (c[n][1] - mu0) * inv0 * gv.y + bt.y;
                *(float2*)(out + (size_t)row0 * FD + col) = make_float2(ox, oy);
            }
            if (row1 < NN) {
                float ox = (c[n][2] - mu1) * inv1 * gv.x + bt.x;
                float oy = (c[n][3] - mu1) * inv1 * gv.y + bt.y;
                *(float2*)(out + (size_t)row1 * FD + col) = make_float2(ox, oy);
            }
        }
    }
}

// ---------------- persistent warp-specialized fused layer ----------------
// 512 threads: warps 0-7 = producers (gather tile t+1), warps 8-15 = consumers
// (GEMM + epilogue tile t). Double-buffered sA; one __syncthreads per step.
template <bool GELU, bool PRESCALE, bool SRCNORM, bool LNORM>
__global__ void __launch_bounds__(512, 1) gcn_fused_kernel(
    const float* __restrict__ hin,
    const float* __restrict__ W,
    const float* __restrict__ bias,
    float* __restrict__ out,
    const float* __restrict__ gamma,
    const float* __restrict__ beta)
{
    extern __shared__ float sm[];
    float* sW  = sm;                          // 128 x SW_STR
    float* sA0 = sm + 128 * SW_STR;           // 64 x SA_STR
    float* sA1 = sA0 + 64 * SA_STR;           // 64 x SA_STR
    __shared__ int    sBnd[8][9];
    __shared__ float2 sLN[64][8];

    int tid  = threadIdx.x;
    int warp = tid >> 5;
    int lane = tid & 31;

    // stage W (all 512 threads)
    {
        float4* sW4 = (float4*)sW;            // row stride 34
        const float4* W4 = (const float4*)W;
        #pragma unroll
        for (int i = 0; i < 8; ++i) {
            int idx = tid + i * 512;          // [0, 4096)
            int k  = idx >> 5;
            int n4 = idx & 31;
            sW4[k * 34 + n4] = __ldg(&W4[idx]);
        }
    }

    const float4* hp = (const float4*)hin;
    int tile = blockIdx.x;

    // prologue: producers gather first tile into sA0
    if (warp < 8) gather_tile<SRCNORM>(hp, tile * 64, warp, lane, sA0, sBnd);
    __syncthreads();

    int buf = 0;
    #pragma unroll 1
    for (; tile < NTILES; tile += GRID_P) {
        int ntile = tile + GRID_P;
        if (warp < 8) {
            if (ntile < NTILES)
                gather_tile<SRCNORM>(hp, ntile * 64, warp, lane,
                                     buf ? sA0 : sA1, sBnd);
        } else {
            gemm_tile<GELU, PRESCALE, LNORM>(
                buf ? sA1 : sA0, sW, tile * 64, warp - 8, lane,
                bias, out, gamma, beta, sLN);
        }
        __syncthreads();
        buf ^= 1;
    }
}

// ---------------- launch ----------------
extern "C" void kernel_launch(void* const* d_in, const int* in_sizes, int n_in,
                              void* d_out, int out_size)
{
    const float* x     = (const float*)d_in[0];
    const int*   src   = (const int*)  d_in[1];
    const int*   dst   = (const int*)  d_in[2];
    const float* Ws[4] = { (const float*)d_in[3], (const float*)d_in[5],
                           (const float*)d_in[7], (const float*)d_in[9] };
    const float* bs[4] = { (const float*)d_in[4], (const float*)d_in[6],
                           (const float*)d_in[8], (const float*)d_in[10] };
    const float* gamma = (const float*)d_in[11];
    const float* beta  = (const float*)d_in[12];
    float* out = (float*)d_out;

    float *h0, *h1;
    cudaGetSymbolAddress((void**)&h0, g_h0);
    cudaGetSymbolAddress((void**)&h1, g_h1);

    cudaFuncSetAttribute(gcn_fused_kernel<true, true, true, false>,
                         cudaFuncAttributeMaxDynamicSharedMemorySize, SMEM_BYTES);
    cudaFuncSetAttribute(gcn_fused_kernel<true, true, false, false>,
                         cudaFuncAttributeMaxDynamicSharedMemorySize, SMEM_BYTES);
    cudaFuncSetAttribute(gcn_fused_kernel<false, false, false, true>,
                         cudaFuncAttributeMaxDynamicSharedMemorySize, SMEM_BYTES);

    const int T = 256;
    zero_counts_kernel<<<(NN + T - 1) / T, T>>>();
    count_deg_kernel<<<(NE + T - 1) / T, T>>>(src, dst);
    make_norm_kernel<<<(NN + T - 1) / T, T>>>();
    scan_block_kernel<<<SCAN_B, SCAN_T>>>();
    scan_bsums_kernel<<<1, 128>>>();
    add_offsets_kernel<<<(NN + T - 1) / T, T>>>();
    fill_csr_kernel<<<(NE + T - 1) / T, T>>>(src, dst);

    gcn_fused_kernel<true, true, true, false><<<GRID_P, 512, SMEM_BYTES>>>(
        x, Ws[0], bs[0], h1, nullptr, nullptr);
    gcn_fused_kernel<true, true, false, false><<<GRID_P, 512, SMEM_BYTES>>>(
        h1, Ws[1], bs[1], h0, nullptr, nullptr);
    gcn_fused_kernel<true, true, false, false><<<GRID_P, 512, SMEM_BYTES>>>(
        h0, Ws[2], bs[2], h1, nullptr, nullptr);
    gcn_fused_kernel<false, false, false, true><<<GRID_P, 512, SMEM_BYTES>>>(
        h1, Ws[3], bs[3], out, gamma, beta);
}

// round 9
// speedup vs baseline: 1.1439x; 1.1439x over previous
#include <cuda_runtime.h>
#include <math.h>
#include <stdint.h>

#define NN 100000
#define NE 1600000
#define FD 128
#define FD4 (FD/4)
#define SCAN_T 1024
#define SCAN_B ((NN + SCAN_T - 1) / SCAN_T)   // 98

// padded smem strides (floats) for bank-conflict-free MMA fragment loads
#define SA_STR 132   // 64 rows
#define SW_STR 136   // 128 rows
#define SMEM_BYTES ((128*SW_STR + 64*SA_STR) * 4)   // 103,424 B
#define ICHUNK 128   // staged indices per warp per chunk

// ---------------- static device scratch ----------------
__device__ float g_h0[(size_t)NN * FD];
__device__ float g_h1[(size_t)NN * FD];
__device__ int   g_cnt_src[NN];
__device__ int   g_cnt_dst[NN];
__device__ float g_norm_src[NN];
__device__ float g_norm_dst[NN];
__device__ int   g_rowstart[NN];
__device__ int   g_fill[NN];
__device__ int   g_bsum[SCAN_B];
__device__ int   g_boff[SCAN_B];
__device__ int   g_csr_src[NE];

// ---------------- setup kernels ----------------
__global__ void zero_counts_kernel() {
    int i = blockIdx.x * blockDim.x + threadIdx.x;
    if (i < NN) { g_cnt_src[i] = 0; g_cnt_dst[i] = 0; }
}

__global__ void count_deg_kernel(const int* __restrict__ src,
                                 const int* __restrict__ dst) {
    int i = blockIdx.x * blockDim.x + threadIdx.x;
    if (i < NE) {
        atomicAdd(&g_cnt_src[src[i]], 1);
        atomicAdd(&g_cnt_dst[dst[i]], 1);
    }
}

__global__ void make_norm_kernel() {
    int i = blockIdx.x * blockDim.x + threadIdx.x;
    if (i < NN) {
        g_norm_src[i] = rsqrtf(fmaxf((float)g_cnt_src[i], 1.0f));
        g_norm_dst[i] = rsqrtf(fmaxf((float)g_cnt_dst[i], 1.0f));
    }
}

__global__ void __launch_bounds__(SCAN_T) scan_block_kernel() {
    __shared__ int s[SCAN_T];
    int t = threadIdx.x;
    int i = blockIdx.x * SCAN_T + t;
    int v = (i < NN) ? g_cnt_dst[i] : 0;
    s[t] = v;
    __syncthreads();
    #pragma unroll
    for (int off = 1; off < SCAN_T; off <<= 1) {
        int x = (t >= off) ? s[t - off] : 0;
        __syncthreads();
        s[t] += x;
        __syncthreads();
    }
    if (i < NN) g_rowstart[i] = s[t] - v;
    if (t == SCAN_T - 1) g_bsum[blockIdx.x] = s[t];
}

__global__ void scan_bsums_kernel() {
    __shared__ int s[128];
    int t = threadIdx.x;
    int v = (t < SCAN_B) ? g_bsum[t] : 0;
    s[t] = v;
    __syncthreads();
    #pragma unroll
    for (int off = 1; off < 128; off <<= 1) {
        int x = (t >= off) ? s[t - off] : 0;
        __syncthreads();
        s[t] += x;
        __syncthreads();
    }
    if (t < SCAN_B) g_boff[t] = s[t] - v;
}

__global__ void add_offsets_kernel() {
    int i = blockIdx.x * blockDim.x + threadIdx.x;
    if (i < NN) {
        int v = g_rowstart[i] + g_boff[i >> 10];
        g_rowstart[i] = v;
        g_fill[i] = v;
    }
}

__global__ void fill_csr_kernel(const int* __restrict__ src,
                                const int* __restrict__ dst) {
    int e = blockIdx.x * blockDim.x + threadIdx.x;
    if (e < NE) {
        int pos = atomicAdd(&g_fill[dst[e]], 1);
        g_csr_src[pos] = src[e];
    }
}

// ---------------- tf32 helpers ----------------
__device__ __forceinline__ void f2tf32_split(float a, uint32_t& hi, uint32_t& lo) {
    asm("cvt.rna.tf32.f32 %0, %1;" : "=r"(hi) : "f"(a));
    float r = a - __uint_as_float(hi);
    asm("cvt.rna.tf32.f32 %0, %1;" : "=r"(lo) : "f"(r));
}

__device__ __forceinline__ void mma_tf32(float* c,
    uint32_t a0, uint32_t a1, uint32_t a2, uint32_t a3,
    uint32_t b0, uint32_t b1)
{
    asm volatile(
        "mma.sync.aligned.m16n8k8.row.col.f32.tf32.tf32.f32 "
        "{%0,%1,%2,%3}, {%4,%5,%6,%7}, {%8,%9}, {%0,%1,%2,%3};"
        : "+f"(c[0]), "+f"(c[1]), "+f"(c[2]), "+f"(c[3])
        : "r"(a0), "r"(a1), "r"(a2), "r"(a3), "r"(b0), "r"(b1));
}

__device__ __forceinline__ float gelu_exact(float x) {
    return 0.5f * x * (1.0f + erff(x * 0.7071067811865476f));
}

// ---------------- fused gather + tensor-core GEMM + epilogue ----------------
// Block: 256 threads (8 warps), 64 output rows x 128 cols, 2 blocks/SM.
// Gather: per-warp contiguous CSR range; indices staged through smem in
//         coalesced 128-edge chunks, then pipelined feature loads (idx via
//         LDS — no L2 latency in the dependency chain).
// GEMM: 3xTF32 mma.sync (fp32-equivalent). Optional fused LayerNorm (layer 4).
template <bool GELU, bool PRESCALE, bool SRCNORM, bool LNORM>
__global__ void __launch_bounds__(256, 2) gcn_fused_kernel(
    const float* __restrict__ hin,
    const float* __restrict__ W,      // [FD, FD] row-major (k, n)
    const float* __restrict__ bias,   // [FD]
    float* __restrict__ out,          // [NN, FD]
    const float* __restrict__ gamma,
    const float* __restrict__ beta)
{
    extern __shared__ float sm[];
    float* sW = sm;                       // 128 x SW_STR
    float* sA = sm + 128 * SW_STR;        // 64  x SA_STR
    __shared__ int sBnd[8][9];            // per-warp row boundaries
    __shared__ int sIdx[8][ICHUNK];       // staged edge indices
    int tid  = threadIdx.x;
    int warp = tid >> 5;
    int lane = tid & 31;
    int rowbase = blockIdx.x * 64;

    // stage W (padded rows)
    {
        float4* sW4 = (float4*)sW;        // row stride SW_STR/4 = 34
        const float4* W4 = (const float4*)W;
        #pragma unroll
        for (int i = 0; i < 16; ++i) {
            int idx = tid + i * 256;
            int k  = idx >> 5;
            int n4 = idx & 31;
            sW4[k * 34 + n4] = __ldg(&W4[idx]);
        }
    }

    // ---- boundary setup: warp w owns rows [r0, r0+8) ----
    int r0 = rowbase + warp * 8;
    {
        int myc = 0;
        int rr = r0 + lane;
        if (lane < 8 && rr < NN) myc = __ldg(&g_cnt_dst[rr]);
        int sum = myc;
        #pragma unroll
        for (int off = 1; off < 8; off <<= 1) {
            int t = __shfl_up_sync(0xFFFFFFFFu, sum, off);
            if ((lane & 7) >= off) sum += t;
        }
        int beg = (r0 < NN) ? __ldg(&g_rowstart[r0]) : 0;
        if (lane == 0) sBnd[warp][0] = beg;
        if (lane < 8)  sBnd[warp][lane + 1] = beg + sum;
    }
    __syncwarp();

    // ---- linear-stream gather with smem-staged indices ----
    {
        const float4* hp = (const float4*)hin;
        int beg = sBnd[warp][0];
        int end = sBnd[warp][8];
        int cur = 0;
        int next = sBnd[warp][1];
        float4 acc = make_float4(0.f, 0.f, 0.f, 0.f);
        float4* sArow = (float4*)sA;      // stride 33 float4
        int* myIdx = sIdx[warp];

        #pragma unroll 1
        for (int cs = beg; cs < end; cs += ICHUNK) {
            int cnt = end - cs;
            if (cnt > ICHUNK) cnt = ICHUNK;
            // coalesced index stage
            #pragma unroll
            for (int i = 0; i < 4; ++i) {
                int j = lane + 32 * i;
                if (j < cnt) myIdx[j] = __ldg(&g_csr_src[cs + j]);
            }
            __syncwarp();

            int j = 0;
            float4 v[8]; float ns[8];
            bool pro = (cnt >= 8);
            if (pro) {
                #pragma unroll
                for (int q = 0; q < 8; ++q) {
                    int s = myIdx[q];
                    if (SRCNORM) ns[q] = __ldg(&g_norm_src[s]);
                    v[q] = __ldg(&hp[s * 32 + lane]);
                }
            }
            #pragma unroll 1
            for (; j + 16 <= cnt; j += 8) {
                float4 w[8]; float ws[8];
                #pragma unroll
                for (int q = 0; q < 8; ++q) {
                    int s = myIdx[j + 8 + q];
                    if (SRCNORM) ws[q] = __ldg(&g_norm_src[s]);
                    w[q] = __ldg(&hp[s * 32 + lane]);
                }
                #pragma unroll
                for (int q = 0; q < 8; ++q) {
                    int ee = cs + j + q;
                    while (ee >= next) {             // warp-uniform
                        sArow[(warp * 8 + cur) * 33 + lane] = acc;
                        acc = make_float4(0.f, 0.f, 0.f, 0.f);
                        ++cur;
                        next = sBnd[warp][cur + 1];
                    }
                    if (SRCNORM) {
                        acc.x += v[q].x * ns[q]; acc.y += v[q].y * ns[q];
                        acc.z += v[q].z * ns[q]; acc.w += v[q].w * ns[q];
                    } else {
                        acc.x += v[q].x; acc.y += v[q].y;
                        acc.z += v[q].z; acc.w += v[q].w;
                    }
                }
                #pragma unroll
                for (int q = 0; q < 8; ++q) { v[q] = w[q]; if (SRCNORM) ns[q] = ws[q]; }
            }
            if (pro) {
                #pragma unroll
                for (int q = 0; q < 8; ++q) {
                    int ee = cs + j + q;
                    while (ee >= next) {
                        sArow[(warp * 8 + cur) * 33 + lane] = acc;
                        acc = make_float4(0.f, 0.f, 0.f, 0.f);
                        ++cur;
                        next = sBnd[warp][cur + 1];
                    }
                    if (SRCNORM) {
                        acc.x += v[q].x * ns[q]; acc.y += v[q].y * ns[q];
                        acc.z += v[q].z * ns[q]; acc.w += v[q].w * ns[q];
                    } else {
                        acc.x += v[q].x; acc.y += v[q].y;
                        acc.z += v[q].z; acc.w += v[q].w;
                    }
                }
                j += 8;
            }
            // remainder (< 8 edges): parallel predicated loads, then consume
            {
                float4 rv[8]; float rns[8]; int have = cnt - j;
                #pragma unroll
                for (int q = 0; q < 8; ++q) {
                    if (q < have) {
                        int s = myIdx[j + q];
                        if (SRCNORM) rns[q] = __ldg(&g_norm_src[s]);
                        rv[q] = __ldg(&hp[s * 32 + lane]);
                    }
                }
                #pragma unroll
                for (int q = 0; q < 8; ++q) {
                    if (q < have) {
                        int ee = cs + j + q;
                        while (ee >= next) {
                            sArow[(warp * 8 + cur) * 33 + lane] = acc;
                            acc = make_float4(0.f, 0.f, 0.f, 0.f);
                            ++cur;
                            next = sBnd[warp][cur + 1];
                        }
                        if (SRCNORM) {
                            acc.x += rv[q].x * rns[q]; acc.y += rv[q].y * rns[q];
                            acc.z += rv[q].z * rns[q]; acc.w += rv[q].w * rns[q];
                        } else {
                            acc.x += rv[q].x; acc.y += rv[q].y;
                            acc.z += rv[q].z; acc.w += rv[q].w;
                        }
                    }
                }
            }
            __syncwarp();   // protect myIdx before next chunk overwrites
        }
        // flush current row and zero-fill remaining rows
        #pragma unroll
        for (int rr = 0; rr < 8; ++rr) {
            if (rr >= cur) {
                sArow[(warp * 8 + rr) * 33 + lane] = acc;
                acc = make_float4(0.f, 0.f, 0.f, 0.f);
            }
        }
    }
    __syncthreads();

    // ---- tensor-core GEMM: D[64x128] = sA[64x128] @ sW[128x128] (3xTF32) ----
    int g = lane >> 2;        // 0..7
    int t = lane & 3;         // 0..3
    int rtbase = (warp & 3) * 16;
    int chbase = (warp >> 2) * 64;

    float c[8][4];
    #pragma unroll
    for (int n = 0; n < 8; ++n)
        #pragma unroll
        for (int j = 0; j < 4; ++j) c[n][j] = 0.f;

    #pragma unroll 4
    for (int k = 0; k < 16; ++k) {
        int k0 = k * 8;
        float a0f = sA[(rtbase + g)     * SA_STR + k0 + t];
        float a1f = sA[(rtbase + g + 8) * SA_STR + k0 + t];
        float a2f = sA[(rtbase + g)     * SA_STR + k0 + t + 4];
        float a3f = sA[(rtbase + g + 8) * SA_STR + k0 + t + 4];
        uint32_t ah0, al0, ah1, al1, ah2, al2, ah3, al3;
        f2tf32_split(a0f, ah0, al0);
        f2tf32_split(a1f, ah1, al1);
        f2tf32_split(a2f, ah2, al2);
        f2tf32_split(a3f, ah3, al3);

        #pragma unroll
        for (int n = 0; n < 8; ++n) {
            int ncol = chbase + n * 8 + g;
            float b0f = sW[(k0 + t)     * SW_STR + ncol];
            float b1f = sW[(k0 + t + 4) * SW_STR + ncol];
            uint32_t bh0, bl0, bh1, bl1;
            f2tf32_split(b0f, bh0, bl0);
            f2tf32_split(b1f, bh1, bl1);

            mma_tf32(c[n], ah0, ah1, ah2, ah3, bh0, bh1);
            mma_tf32(c[n], ah0, ah1, ah2, ah3, bl0, bl1);
            mma_tf32(c[n], al0, al1, al2, al3, bh0, bh1);
        }
    }

    // ---- epilogue ----
    int row0 = rowbase + rtbase + g;
    int row1 = row0 + 8;
    float nd0 = 0.f, nd1 = 0.f, ns0 = 1.f, ns1 = 1.f;
    if (row0 < NN) { nd0 = __ldg(&g_norm_dst[row0]); if (PRESCALE) ns0 = __ldg(&g_norm_src[row0]); }
    if (row1 < NN) { nd1 = __ldg(&g_norm_dst[row1]); if (PRESCALE) ns1 = __ldg(&g_norm_src[row1]); }

    if (!LNORM) {
        #pragma unroll
        for (int n = 0; n < 8; ++n) {
            int col = chbase + n * 8 + t * 2;
            float2 bv = *(const float2*)(bias + col);
            if (row0 < NN) {
                float ox = c[n][0] * nd0 + bv.x;
                float oy = c[n][1] * nd0 + bv.y;
                if (GELU) { ox = gelu_exact(ox); oy = gelu_exact(oy); }
                if (PRESCALE) { ox *= ns0; oy *= ns0; }
                *(float2*)(out + (size_t)row0 * FD + col) = make_float2(ox, oy);
            }
            if (row1 < NN) {
                float ox = c[n][2] * nd1 + bv.x;
                float oy = c[n][3] * nd1 + bv.y;
                if (GELU) { ox = gelu_exact(ox); oy = gelu_exact(oy); }
                if (PRESCALE) { ox *= ns1; oy *= ns1; }
                *(float2*)(out + (size_t)row1 * FD + col) = make_float2(ox, oy);
            }
        }
    } else {
        float s0 = 0.f, q0 = 0.f, s1 = 0.f, q1 = 0.f;
        #pragma unroll
        for (int n = 0; n < 8; ++n) {
            int col = chbase + n * 8 + t * 2;
            float2 bv = *(const float2*)(bias + col);
            float h00 = c[n][0] * nd0 + bv.x;
            float h01 = c[n][1] * nd0 + bv.y;
            float h10 = c[n][2] * nd1 + bv.x;
            float h11 = c[n][3] * nd1 + bv.y;
            c[n][0] = h00; c[n][1] = h01; c[n][2] = h10; c[n][3] = h11;
            s0 += h00 + h01; q0 += h00 * h00 + h01 * h01;
            s1 += h10 + h11; q1 += h10 * h10 + h11 * h11;
        }
        __syncthreads();
        float2* sLN = (float2*)sA;          // [64][8]
        int slot = (warp >> 2) * 4 + t;
        sLN[(rtbase + g) * 8 + slot]     = make_float2(s0, q0);
        sLN[(rtbase + g + 8) * 8 + slot] = make_float2(s1, q1);
        __syncthreads();
        float ts0 = 0.f, tq0 = 0.f, ts1 = 0.f, tq1 = 0.f;
        #pragma unroll
        for (int k = 0; k < 8; ++k) {
            float2 p0 = sLN[(rtbase + g) * 8 + k];
            float2 p1 = sLN[(rtbase + g + 8) * 8 + k];
            ts0 += p0.x; tq0 += p0.y;
            ts1 += p1.x; tq1 += p1.y;
        }
        float mu0 = ts0 * (1.0f / FD);
        float mu1 = ts1 * (1.0f / FD);
        float inv0 = rsqrtf(fmaxf(tq0 * (1.0f / FD) - mu0 * mu0, 0.f) + 1e-5f);
        float inv1 = rsqrtf(fmaxf(tq1 * (1.0f / FD) - mu1 * mu1, 0.f) + 1e-5f);
        #pragma unroll
        for (int n = 0; n < 8; ++n) {
            int col = chbase + n * 8 + t * 2;
            float2 gv = *(const float2*)(gamma + col);
            float2 bt = *(const float2*)(beta + col);
            if (row0 < NN) {
                float ox = (c[n][0] - mu0) * inv0 * gv.x + bt.x;
                float oy = (c[n][1] - mu0) * inv0 * gv.y + bt.y;
                *(float2*)(out + (size_t)row0 * FD + col) = make_float2(ox, oy);
            }
            if (row1 < NN) {
                float ox = (c[n][2] - mu1) * inv1 * gv.x + bt.x;
                float oy = (c[n][3] - mu1) * inv1 * gv.y + bt.y;
                *(float2*)(out + (size_t)row1 * FD + col) = make_float2(ox, oy);
            }
        }
    }
}

// ---------------- launch ----------------
extern "C" void kernel_launch(void* const* d_in, const int* in_sizes, int n_in,
                              void* d_out, int out_size)
{
    const float* x     = (const float*)d_in[0];
    const int*   src   = (const int*)  d_in[1];
    const int*   dst   = (const int*)  d_in[2];
    const float* Ws[4] = { (const float*)d_in[3], (const float*)d_in[5],
                           (const float*)d_in[7], (const float*)d_in[9] };
    const float* bs[4] = { (const float*)d_in[4], (const float*)d_in[6],
                           (const float*)d_in[8], (const float*)d_in[10] };
    const float* gamma = (const float*)d_in[11];
    const float* beta  = (const float*)d_in[12];
    float* out = (float*)d_out;

    float *h0, *h1;
    cudaGetSymbolAddress((void**)&h0, g_h0);
    cudaGetSymbolAddress((void**)&h1, g_h1);

    cudaFuncSetAttribute(gcn_fused_kernel<true, true, true, false>,
                         cudaFuncAttributeMaxDynamicSharedMemorySize, SMEM_BYTES);
    cudaFuncSetAttribute(gcn_fused_kernel<true, true, false, false>,
                         cudaFuncAttributeMaxDynamicSharedMemorySize, SMEM_BYTES);
    cudaFuncSetAttribute(gcn_fused_kernel<false, false, false, true>,
                         cudaFuncAttributeMaxDynamicSharedMemorySize, SMEM_BYTES);

    const int T = 256;
    zero_counts_kernel<<<(NN + T - 1) / T, T>>>();
    count_deg_kernel<<<(NE + T - 1) / T, T>>>(src, dst);
    make_norm_kernel<<<(NN + T - 1) / T, T>>>();
    scan_block_kernel<<<SCAN_B, SCAN_T>>>();
    scan_bsums_kernel<<<1, 128>>>();
    add_offsets_kernel<<<(NN + T - 1) / T, T>>>();
    fill_csr_kernel<<<(NE + T - 1) / T, T>>>(src, dst);

    const int gemm_blocks = (NN + 63) / 64;
    gcn_fused_kernel<true, true, true, false><<<gemm_blocks, T, SMEM_BYTES>>>(
        x, Ws[0], bs[0], h1, nullptr, nullptr);
    gcn_fused_kernel<true, true, false, false><<<gemm_blocks, T, SMEM_BYTES>>>(
        h1, Ws[1], bs[1], h0, nullptr, nullptr);
    gcn_fused_kernel<true, true, false, false><<<gemm_blocks, T, SMEM_BYTES>>>(
        h0, Ws[2], bs[2], h1, nullptr, nullptr);
    gcn_fused_kernel<false, false, false, true><<<gemm_blocks, T, SMEM_BYTES>>>(
        h1, Ws[3], bs[3], out, gamma, beta);
}

// round 10
// speedup vs baseline: 1.2715x; 1.1115x over previous
#include <cuda_runtime.h>
#include <cuda_fp16.h>
#include <math.h>
#include <stdint.h>

#define NN 100000
#define NE 1600000
#define FD 128
#define FD4 (FD/4)
#define SCAN_T 1024
#define SCAN_B ((NN + SCAN_T - 1) / SCAN_T)   // 98

// padded smem strides (floats) for bank-conflict-free MMA fragment loads
#define SA_STR 132   // 64 rows
#define SW_STR 136   // 128 rows
#define SMEM_BYTES ((128*SW_STR + 64*SA_STR) * 4)   // 103,424 B
#define ICHUNK 128   // staged indices per warp per chunk

// ---------------- static device scratch ----------------
__device__ __half g_hh0[(size_t)NN * FD];   // fp16 activations (ping)
__device__ __half g_hh1[(size_t)NN * FD];   // fp16 activations (pong)
__device__ int   g_cnt_src[NN];
__device__ int   g_cnt_dst[NN];
__device__ float g_norm_src[NN];
__device__ float g_norm_dst[NN];
__device__ int   g_rowstart[NN];
__device__ int   g_fill[NN];
__device__ int   g_bsum[SCAN_B];
__device__ int   g_boff[SCAN_B];
__device__ int   g_csr_src[NE];

// ---------------- setup kernels ----------------
__global__ void zero_counts_kernel() {
    int i = blockIdx.x * blockDim.x + threadIdx.x;
    if (i < NN) { g_cnt_src[i] = 0; g_cnt_dst[i] = 0; }
}

__global__ void count_deg_kernel(const int* __restrict__ src,
                                 const int* __restrict__ dst) {
    int i = blockIdx.x * blockDim.x + threadIdx.x;
    if (i < NE) {
        atomicAdd(&g_cnt_src[src[i]], 1);
        atomicAdd(&g_cnt_dst[dst[i]], 1);
    }
}

__global__ void make_norm_kernel() {
    int i = blockIdx.x * blockDim.x + threadIdx.x;
    if (i < NN) {
        g_norm_src[i] = rsqrtf(fmaxf((float)g_cnt_src[i], 1.0f));
        g_norm_dst[i] = rsqrtf(fmaxf((float)g_cnt_dst[i], 1.0f));
    }
}

__global__ void __launch_bounds__(SCAN_T) scan_block_kernel() {
    __shared__ int s[SCAN_T];
    int t = threadIdx.x;
    int i = blockIdx.x * SCAN_T + t;
    int v = (i < NN) ? g_cnt_dst[i] : 0;
    s[t] = v;
    __syncthreads();
    #pragma unroll
    for (int off = 1; off < SCAN_T; off <<= 1) {
        int x = (t >= off) ? s[t - off] : 0;
        __syncthreads();
        s[t] += x;
        __syncthreads();
    }
    if (i < NN) g_rowstart[i] = s[t] - v;
    if (t == SCAN_T - 1) g_bsum[blockIdx.x] = s[t];
}

__global__ void scan_bsums_kernel() {
    __shared__ int s[128];
    int t = threadIdx.x;
    int v = (t < SCAN_B) ? g_bsum[t] : 0;
    s[t] = v;
    __syncthreads();
    #pragma unroll
    for (int off = 1; off < 128; off <<= 1) {
        int x = (t >= off) ? s[t - off] : 0;
        __syncthreads();
        s[t] += x;
        __syncthreads();
    }
    if (t < SCAN_B) g_boff[t] = s[t] - v;
}

__global__ void add_offsets_kernel() {
    int i = blockIdx.x * blockDim.x + threadIdx.x;
    if (i < NN) {
        int v = g_rowstart[i] + g_boff[i >> 10];
        g_rowstart[i] = v;
        g_fill[i] = v;
    }
}

__global__ void fill_csr_kernel(const int* __restrict__ src,
                                const int* __restrict__ dst) {
    int e = blockIdx.x * blockDim.x + threadIdx.x;
    if (e < NE) {
        int pos = atomicAdd(&g_fill[dst[e]], 1);
        g_csr_src[pos] = src[e];
    }
}

// convert x*norm_src -> fp16
__global__ void convert_x_kernel(const float* __restrict__ x, __half* __restrict__ o) {
    int i = blockIdx.x * blockDim.x + threadIdx.x;
    if (i < NN * FD4) {
        int row = i >> 5;
        float ns = __ldg(&g_norm_src[row]);
        float4 v = __ldg(&((const float4*)x)[i]);
        __half2 a = __floats2half2_rn(v.x * ns, v.y * ns);
        __half2 b = __floats2half2_rn(v.z * ns, v.w * ns);
        uint2 packed;
        packed.x = *(uint32_t*)&a;
        packed.y = *(uint32_t*)&b;
        ((uint2*)o)[i] = packed;
    }
}

// ---------------- tf32 helpers ----------------
__device__ __forceinline__ void f2tf32_split(float a, uint32_t& hi, uint32_t& lo) {
    asm("cvt.rna.tf32.f32 %0, %1;" : "=r"(hi) : "f"(a));
    float r = a - __uint_as_float(hi);
    asm("cvt.rna.tf32.f32 %0, %1;" : "=r"(lo) : "f"(r));
}

__device__ __forceinline__ void mma_tf32(float* c,
    uint32_t a0, uint32_t a1, uint32_t a2, uint32_t a3,
    uint32_t b0, uint32_t b1)
{
    asm volatile(
        "mma.sync.aligned.m16n8k8.row.col.f32.tf32.tf32.f32 "
        "{%0,%1,%2,%3}, {%4,%5,%6,%7}, {%8,%9}, {%0,%1,%2,%3};"
        : "+f"(c[0]), "+f"(c[1]), "+f"(c[2]), "+f"(c[3])
        : "r"(a0), "r"(a1), "r"(a2), "r"(a3), "r"(b0), "r"(b1));
}

__device__ __forceinline__ float gelu_exact(float x) {
    return 0.5f * x * (1.0f + erff(x * 0.7071067811865476f));
}

__device__ __forceinline__ void acc_h4(float4& acc, uint2 raw) {
    __half2 ha = *(__half2*)&raw.x;
    __half2 hb = *(__half2*)&raw.y;
    float2 fa = __half22float2(ha);
    float2 fb = __half22float2(hb);
    acc.x += fa.x; acc.y += fa.y; acc.z += fb.x; acc.w += fb.y;
}

// ---------------- fused gather + tensor-core GEMM + epilogue ----------------
// Block: 256 threads (8 warps), 64 output rows x 128 cols, 2 blocks/SM.
// Gather: per-warp contiguous CSR range; indices staged through smem; fp16
//         features (4 halves per lane per edge), fp32 accumulation.
// GEMM: 3xTF32 mma.sync. Epilogue: fp16 h output (L1-L3) or fp32+LN (L4).
template <bool GELU, bool PRESCALE, bool LNORM>
__global__ void __launch_bounds__(256, 2) gcn_fused_kernel(
    const __half* __restrict__ hin,   // [NN, FD] fp16, already *norm_src
    const float* __restrict__ W,      // [FD, FD] row-major (k, n)
    const float* __restrict__ bias,   // [FD]
    __half* __restrict__ outh,        // fp16 out (L1-L3)
    float* __restrict__ outf,         // fp32 out (L4)
    const float* __restrict__ gamma,
    const float* __restrict__ beta)
{
    extern __shared__ float sm[];
    float* sW = sm;                       // 128 x SW_STR
    float* sA = sm + 128 * SW_STR;        // 64  x SA_STR
    __shared__ int sBnd[8][9];            // per-warp row boundaries
    __shared__ int sIdx[8][ICHUNK];       // staged edge indices
    int tid  = threadIdx.x;
    int warp = tid >> 5;
    int lane = tid & 31;
    int rowbase = blockIdx.x * 64;

    // stage W (padded rows)
    {
        float4* sW4 = (float4*)sW;        // row stride SW_STR/4 = 34
        const float4* W4 = (const float4*)W;
        #pragma unroll
        for (int i = 0; i < 16; ++i) {
            int idx = tid + i * 256;
            int k  = idx >> 5;
            int n4 = idx & 31;
            sW4[k * 34 + n4] = __ldg(&W4[idx]);
        }
    }

    // ---- boundary setup: warp w owns rows [r0, r0+8) ----
    int r0 = rowbase + warp * 8;
    {
        int myc = 0;
        int rr = r0 + lane;
        if (lane < 8 && rr < NN) myc = __ldg(&g_cnt_dst[rr]);
        int sum = myc;
        #pragma unroll
        for (int off = 1; off < 8; off <<= 1) {
            int t = __shfl_up_sync(0xFFFFFFFFu, sum, off);
            if ((lane & 7) >= off) sum += t;
        }
        int beg = (r0 < NN) ? __ldg(&g_rowstart[r0]) : 0;
        if (lane == 0) sBnd[warp][0] = beg;
        if (lane < 8)  sBnd[warp][lane + 1] = beg + sum;
    }
    __syncwarp();

    // ---- linear-stream gather (fp16 features, smem-staged indices) ----
    {
        const uint2* hp = (const uint2*)hin;   // row = 32 uint2 (256 B)
        int beg = sBnd[warp][0];
        int end = sBnd[warp][8];
        int cur = 0;
        int next = sBnd[warp][1];
        float4 acc = make_float4(0.f, 0.f, 0.f, 0.f);
        float4* sArow = (float4*)sA;      // stride 33 float4
        int* myIdx = sIdx[warp];

        #pragma unroll 1
        for (int cs = beg; cs < end; cs += ICHUNK) {
            int cnt = end - cs;
            if (cnt > ICHUNK) cnt = ICHUNK;
            // coalesced index stage
            #pragma unroll
            for (int i = 0; i < 4; ++i) {
                int j = lane + 32 * i;
                if (j < cnt) myIdx[j] = __ldg(&g_csr_src[cs + j]);
            }
            __syncwarp();

            int j = 0;
            uint2 v[8];
            bool pro = (cnt >= 8);
            if (pro) {
                #pragma unroll
                for (int q = 0; q < 8; ++q) {
                    int s = myIdx[q];
                    v[q] = __ldg(&hp[s * 32 + lane]);
                }
            }
            #pragma unroll 1
            for (; j + 16 <= cnt; j += 8) {
                uint2 w[8];
                #pragma unroll
                for (int q = 0; q < 8; ++q) {
                    int s = myIdx[j + 8 + q];
                    w[q] = __ldg(&hp[s * 32 + lane]);
                }
                #pragma unroll
                for (int q = 0; q < 8; ++q) {
                    int ee = cs + j + q;
                    while (ee >= next) {             // warp-uniform
                        sArow[(warp * 8 + cur) * 33 + lane] = acc;
                        acc = make_float4(0.f, 0.f, 0.f, 0.f);
                        ++cur;
                        next = sBnd[warp][cur + 1];
                    }
                    acc_h4(acc, v[q]);
                }
                #pragma unroll
                for (int q = 0; q < 8; ++q) v[q] = w[q];
            }
            if (pro) {
                #pragma unroll
                for (int q = 0; q < 8; ++q) {
                    int ee = cs + j + q;
                    while (ee >= next) {
                        sArow[(warp * 8 + cur) * 33 + lane] = acc;
                        acc = make_float4(0.f, 0.f, 0.f, 0.f);
                        ++cur;
                        next = sBnd[warp][cur + 1];
                    }
                    acc_h4(acc, v[q]);
                }
                j += 8;
            }
            // remainder (< 8 edges): parallel predicated loads, then consume
            {
                uint2 rv[8]; int have = cnt - j;
                #pragma unroll
                for (int q = 0; q < 8; ++q) {
                    if (q < have) {
                        int s = myIdx[j + q];
                        rv[q] = __ldg(&hp[s * 32 + lane]);
                    }
                }
                #pragma unroll
                for (int q = 0; q < 8; ++q) {
                    if (q < have) {
                        int ee = cs + j + q;
                        while (ee >= next) {
                            sArow[(warp * 8 + cur) * 33 + lane] = acc;
                            acc = make_float4(0.f, 0.f, 0.f, 0.f);
                            ++cur;
                            next = sBnd[warp][cur + 1];
                        }
                        acc_h4(acc, rv[q]);
                    }
                }
            }
            __syncwarp();   // protect myIdx before next chunk overwrites
        }
        // flush current row and zero-fill remaining rows
        #pragma unroll
        for (int rr = 0; rr < 8; ++rr) {
            if (rr >= cur) {
                sArow[(warp * 8 + rr) * 33 + lane] = acc;
                acc = make_float4(0.f, 0.f, 0.f, 0.f);
            }
        }
    }
    __syncthreads();

    // ---- tensor-core GEMM: D[64x128] = sA[64x128] @ sW[128x128] (3xTF32) ----
    int g = lane >> 2;        // 0..7
    int t = lane & 3;         // 0..3
    int rtbase = (warp & 3) * 16;
    int chbase = (warp >> 2) * 64;

    float c[8][4];
    #pragma unroll
    for (int n = 0; n < 8; ++n)
        #pragma unroll
        for (int j = 0; j < 4; ++j) c[n][j] = 0.f;

    #pragma unroll 4
    for (int k = 0; k < 16; ++k) {
        int k0 = k * 8;
        float a0f = sA[(rtbase + g)     * SA_STR + k0 + t];
        float a1f = sA[(rtbase + g + 8) * SA_STR + k0 + t];
        float a2f = sA[(rtbase + g)     * SA_STR + k0 + t + 4];
        float a3f = sA[(rtbase + g + 8) * SA_STR + k0 + t + 4];
        uint32_t ah0, al0, ah1, al1, ah2, al2, ah3, al3;
        f2tf32_split(a0f, ah0, al0);
        f2tf32_split(a1f, ah1, al1);
        f2tf32_split(a2f, ah2, al2);
        f2tf32_split(a3f, ah3, al3);

        #pragma unroll
        for (int n = 0; n < 8; ++n) {
            int ncol = chbase + n * 8 + g;
            float b0f = sW[(k0 + t)     * SW_STR + ncol];
            float b1f = sW[(k0 + t + 4) * SW_STR + ncol];
            uint32_t bh0, bl0, bh1, bl1;
            f2tf32_split(b0f, bh0, bl0);
            f2tf32_split(b1f, bh1, bl1);

            mma_tf32(c[n], ah0, ah1, ah2, ah3, bh0, bh1);
            mma_tf32(c[n], ah0, ah1, ah2, ah3, bl0, bl1);
            mma_tf32(c[n], al0, al1, al2, al3, bh0, bh1);
        }
    }

    // ---- epilogue ----
    int row0 = rowbase + rtbase + g;
    int row1 = row0 + 8;
    float nd0 = 0.f, nd1 = 0.f, ns0 = 1.f, ns1 = 1.f;
    if (row0 < NN) { nd0 = __ldg(&g_norm_dst[row0]); if (PRESCALE) ns0 = __ldg(&g_norm_src[row0]); }
    if (row1 < NN) { nd1 = __ldg(&g_norm_dst[row1]); if (PRESCALE) ns1 = __ldg(&g_norm_src[row1]); }

    if (!LNORM) {
        #pragma unroll
        for (int n = 0; n < 8; ++n) {
            int col = chbase + n * 8 + t * 2;
            float2 bv = *(const float2*)(bias + col);
            if (row0 < NN) {
                float ox = c[n][0] * nd0 + bv.x;
                float oy = c[n][1] * nd0 + bv.y;
                if (GELU) { ox = gelu_exact(ox); oy = gelu_exact(oy); }
                if (PRESCALE) { ox *= ns0; oy *= ns0; }
                ((__half2*)outh)[row0 * 64 + (col >> 1)] = __floats2half2_rn(ox, oy);
            }
            if (row1 < NN) {
                float ox = c[n][2] * nd1 + bv.x;
                float oy = c[n][3] * nd1 + bv.y;
                if (GELU) { ox = gelu_exact(ox); oy = gelu_exact(oy); }
                if (PRESCALE) { ox *= ns1; oy *= ns1; }
                ((__half2*)outh)[row1 * 64 + (col >> 1)] = __floats2half2_rn(ox, oy);
            }
        }
    } else {
        float s0 = 0.f, q0 = 0.f, s1 = 0.f, q1 = 0.f;
        #pragma unroll
        for (int n = 0; n < 8; ++n) {
            int col = chbase + n * 8 + t * 2;
            float2 bv = *(const float2*)(bias + col);
            float h00 = c[n][0] * nd0 + bv.x;
            float h01 = c[n][1] * nd0 + bv.y;
            float h10 = c[n][2] * nd1 + bv.x;
            float h11 = c[n][3] * nd1 + bv.y;
            c[n][0] = h00; c[n][1] = h01; c[n][2] = h10; c[n][3] = h11;
            s0 += h00 + h01; q0 += h00 * h00 + h01 * h01;
            s1 += h10 + h11; q1 += h10 * h10 + h11 * h11;
        }
        __syncthreads();
        float2* sLN = (float2*)sA;          // [64][8]
        int slot = (warp >> 2) * 4 + t;
        sLN[(rtbase + g) * 8 + slot]     = make_float2(s0, q0);
        sLN[(rtbase + g + 8) * 8 + slot] = make_float2(s1, q1);
        __syncthreads();
        float ts0 = 0.f, tq0 = 0.f, ts1 = 0.f, tq1 = 0.f;
        #pragma unroll
        for (int k = 0; k < 8; ++k) {
            float2 p0 = sLN[(rtbase + g) * 8 + k];
            float2 p1 = sLN[(rtbase + g + 8) * 8 + k];
            ts0 += p0.x; tq0 += p0.y;
            ts1 += p1.x; tq1 += p1.y;
        }
        float mu0 = ts0 * (1.0f / FD);
        float mu1 = ts1 * (1.0f / FD);
        float inv0 = rsqrtf(fmaxf(tq0 * (1.0f / FD) - mu0 * mu0, 0.f) + 1e-5f);
        float inv1 = rsqrtf(fmaxf(tq1 * (1.0f / FD) - mu1 * mu1, 0.f) + 1e-5f);
        #pragma unroll
        for (int n = 0; n < 8; ++n) {
            int col = chbase + n * 8 + t * 2;
            float2 gv = *(const float2*)(gamma + col);
            float2 bt = *(const float2*)(beta + col);
            if (row0 < NN) {
                float ox = (c[n][0] - mu0) * inv0 * gv.x + bt.x;
                float oy = (c[n][1] - mu0) * inv0 * gv.y + bt.y;
                *(float2*)(outf + (size_t)row0 * FD + col) = make_float2(ox, oy);
            }
            if (row1 < NN) {
                float ox = (c[n][2] - mu1) * inv1 * gv.x + bt.x;
                float oy = (c[n][3] - mu1) * inv1 * gv.y + bt.y;
                *(float2*)(outf + (size_t)row1 * FD + col) = make_float2(ox, oy);
            }
        }
    }
}

// ---------------- launch ----------------
extern "C" void kernel_launch(void* const* d_in, const int* in_sizes, int n_in,
                              void* d_out, int out_size)
{
    const float* x     = (const float*)d_in[0];
    const int*   src   = (const int*)  d_in[1];
    const int*   dst   = (const int*)  d_in[2];
    const float* Ws[4] = { (const float*)d_in[3], (const float*)d_in[5],
                           (const float*)d_in[7], (const float*)d_in[9] };
    const float* bs[4] = { (const float*)d_in[4], (const float*)d_in[6],
                           (const float*)d_in[8], (const float*)d_in[10] };
    const float* gamma = (const float*)d_in[11];
    const float* beta  = (const float*)d_in[12];
    float* out = (float*)d_out;

    __half *h0, *h1;
    cudaGetSymbolAddress((void**)&h0, g_hh0);
    cudaGetSymbolAddress((void**)&h1, g_hh1);

    cudaFuncSetAttribute(gcn_fused_kernel<true, true, false>,
                         cudaFuncAttributeMaxDynamicSharedMemorySize, SMEM_BYTES);
    cudaFuncSetAttribute(gcn_fused_kernel<false, false, true>,
                         cudaFuncAttributeMaxDynamicSharedMemorySize, SMEM_BYTES);

    const int T = 256;
    zero_counts_kernel<<<(NN + T - 1) / T, T>>>();
    count_deg_kernel<<<(NE + T - 1) / T, T>>>(src, dst);
    make_norm_kernel<<<(NN + T - 1) / T, T>>>();
    scan_block_kernel<<<SCAN_B, SCAN_T>>>();
    scan_bsums_kernel<<<1, 128>>>();
    add_offsets_kernel<<<(NN + T - 1) / T, T>>>();
    fill_csr_kernel<<<(NE + T - 1) / T, T>>>(src, dst);

    // x * norm_src -> fp16 h0
    convert_x_kernel<<<(NN * FD4 + T - 1) / T, T>>>(x, h0);

    const int gemm_blocks = (NN + 63) / 64;
    gcn_fused_kernel<true, true, false><<<gemm_blocks, T, SMEM_BYTES>>>(
        h0, Ws[0], bs[0], h1, nullptr, nullptr, nullptr);
    gcn_fused_kernel<true, true, false><<<gemm_blocks, T, SMEM_BYTES>>>(
        h1, Ws[1], bs[1], h0, nullptr, nullptr, nullptr);
    gcn_fused_kernel<true, true, false><<<gemm_blocks, T, SMEM_BYTES>>>(
        h0, Ws[2], bs[2], h1, nullptr, nullptr, nullptr);
    gcn_fused_kernel<false, false, true><<<gemm_blocks, T, SMEM_BYTES>>>(
        h1, Ws[3], bs[3], nullptr, out, gamma, beta);
}

// round 12
// speedup vs baseline: 1.3649x; 1.0735x over previous
#include <cuda_runtime.h>
#include <cuda_fp16.h>
#include <math.h>
#include <stdint.h>

#define NN 100000
#define NE 1600000
#define FD 128
#define FD4 (FD/4)
#define SCAN_T 1024
#define SCAN_B ((NN + SCAN_T - 1) / SCAN_T)   // 98

// fp16 smem strides (in halves): pad so MMA fragment loads are conflict-free
#define SH_STR 136                    // 272 B per row; word idx = 4g+t unique
#define SMEM_BYTES ((128*SH_STR + 64*SH_STR) * 2)   // 52,224 B
#define ICHUNK 128   // staged indices per warp per chunk

// ---------------- static device scratch ----------------
__device__ __half g_hh0[(size_t)NN * FD];   // fp16 activations (ping)
__device__ __half g_hh1[(size_t)NN * FD];   // fp16 activations (pong)
__device__ int   g_cnt_src[NN];
__device__ int   g_cnt_dst[NN];
__device__ float g_norm_src[NN];
__device__ float g_norm_dst[NN];
__device__ int   g_rowstart[NN];
__device__ int   g_fill[NN];
__device__ int   g_bsum[SCAN_B];
__device__ int   g_boff[SCAN_B];
__device__ int   g_csr_src[NE];

// ---------------- setup kernels ----------------
__global__ void zero_counts_kernel() {
    int i = blockIdx.x * blockDim.x + threadIdx.x;
    if (i < NN) { g_cnt_src[i] = 0; g_cnt_dst[i] = 0; }
}

__global__ void count_deg_kernel(const int* __restrict__ src,
                                 const int* __restrict__ dst) {
    int i = blockIdx.x * blockDim.x + threadIdx.x;
    if (i < NE) {
        atomicAdd(&g_cnt_src[src[i]], 1);
        atomicAdd(&g_cnt_dst[dst[i]], 1);
    }
}

__global__ void make_norm_kernel() {
    int i = blockIdx.x * blockDim.x + threadIdx.x;
    if (i < NN) {
        g_norm_src[i] = rsqrtf(fmaxf((float)g_cnt_src[i], 1.0f));
        g_norm_dst[i] = rsqrtf(fmaxf((float)g_cnt_dst[i], 1.0f));
    }
}

__global__ void __launch_bounds__(SCAN_T) scan_block_kernel() {
    __shared__ int s[SCAN_T];
    int t = threadIdx.x;
    int i = blockIdx.x * SCAN_T + t;
    int v = (i < NN) ? g_cnt_dst[i] : 0;
    s[t] = v;
    __syncthreads();
    #pragma unroll
    for (int off = 1; off < SCAN_T; off <<= 1) {
        int x = (t >= off) ? s[t - off] : 0;
        __syncthreads();
        s[t] += x;
        __syncthreads();
    }
    if (i < NN) g_rowstart[i] = s[t] - v;
    if (t == SCAN_T - 1) g_bsum[blockIdx.x] = s[t];
}

__global__ void scan_bsums_kernel() {
    __shared__ int s[128];
    int t = threadIdx.x;
    int v = (t < SCAN_B) ? g_bsum[t] : 0;
    s[t] = v;
    __syncthreads();
    #pragma unroll
    for (int off = 1; off < 128; off <<= 1) {
        int x = (t >= off) ? s[t - off] : 0;
        __syncthreads();
        s[t] += x;
        __syncthreads();
    }
    if (t < SCAN_B) g_boff[t] = s[t] - v;
}

__global__ void add_offsets_kernel() {
    int i = blockIdx.x * blockDim.x + threadIdx.x;
    if (i < NN) {
        int v = g_rowstart[i] + g_boff[i >> 10];
        g_rowstart[i] = v;
        g_fill[i] = v;
    }
}

__global__ void fill_csr_kernel(const int* __restrict__ src,
                                const int* __restrict__ dst) {
    int e = blockIdx.x * blockDim.x + threadIdx.x;
    if (e < NE) {
        int pos = atomicAdd(&g_fill[dst[e]], 1);
        g_csr_src[pos] = src[e];
    }
}

// convert x*norm_src -> fp16
__global__ void convert_x_kernel(const float* __restrict__ x, __half* __restrict__ o) {
    int i = blockIdx.x * blockDim.x + threadIdx.x;
    if (i < NN * FD4) {
        int row = i >> 5;
        float ns = __ldg(&g_norm_src[row]);
        float4 v = __ldg(&((const float4*)x)[i]);
        __half2 a = __floats2half2_rn(v.x * ns, v.y * ns);
        __half2 b = __floats2half2_rn(v.z * ns, v.w * ns);
        uint2 packed;
        packed.x = *(uint32_t*)&a;
        packed.y = *(uint32_t*)&b;
        ((uint2*)o)[i] = packed;
    }
}

// ---------------- helpers ----------------
__device__ __forceinline__ void mma_f16(float* c,
    uint32_t a0, uint32_t a1, uint32_t a2, uint32_t a3,
    uint32_t b0, uint32_t b1)
{
    asm volatile(
        "mma.sync.aligned.m16n8k16.row.col.f32.f16.f16.f32 "
        "{%0,%1,%2,%3}, {%4,%5,%6,%7}, {%8,%9}, {%0,%1,%2,%3};"
        : "+f"(c[0]), "+f"(c[1]), "+f"(c[2]), "+f"(c[3])
        : "r"(a0), "r"(a1), "r"(a2), "r"(a3), "r"(b0), "r"(b1));
}

__device__ __forceinline__ float gelu_exact(float x) {
    return 0.5f * x * (1.0f + erff(x * 0.7071067811865476f));
}

__device__ __forceinline__ void acc_h4(float4& acc, uint2 raw) {
    __half2 ha = *(__half2*)&raw.x;
    __half2 hb = *(__half2*)&raw.y;
    float2 fa = __half22float2(ha);
    float2 fb = __half22float2(hb);
    acc.x += fa.x; acc.y += fa.y; acc.z += fb.x; acc.w += fb.y;
}

// flush fp32 accumulator to fp16 sA row (4 halves per lane)
__device__ __forceinline__ void flush_row(__half* sA, int row, int lane, float4 acc) {
    __half2 a = __floats2half2_rn(acc.x, acc.y);
    __half2 b = __floats2half2_rn(acc.z, acc.w);
    uint2 p;
    p.x = *(uint32_t*)&a;
    p.y = *(uint32_t*)&b;
    *(uint2*)(sA + row * SH_STR + lane * 4) = p;
}

// ---------------- fused gather + fp16 tensor-core GEMM + epilogue ----------------
// Block: 256 threads (8 warps), 64 output rows x 128 cols, 2 blocks/SM.
// Gather: per-warp contiguous CSR range; smem-staged indices; fp16 features,
//         fp32 accumulation, flushed to fp16 sA.
// GEMM: mma.m16n8k16 f16 (fp32 accum), W transposed fp16 in smem.
template <bool GELU, bool PRESCALE, bool LNORM>
__global__ void __launch_bounds__(256, 2) gcn_fused_kernel(
    const __half* __restrict__ hin,   // [NN, FD] fp16, already *norm_src
    const float* __restrict__ W,      // [FD, FD] row-major (k, n)
    const float* __restrict__ bias,   // [FD]
    __half* __restrict__ outh,        // fp16 out (L1-L3)
    float* __restrict__ outf,         // fp32 out (L4)
    const float* __restrict__ gamma,
    const float* __restrict__ beta)
{
    extern __shared__ __half smh[];
    __half* sWt = smh;                    // [128 n][SH_STR k] transposed W
    __half* sA  = smh + 128 * SH_STR;     // [64 row][SH_STR k]
    __shared__ int sBnd[8][9];            // per-warp row boundaries
    __shared__ int sIdx[8][ICHUNK];       // staged edge indices
    int tid  = threadIdx.x;
    int warp = tid >> 5;
    int lane = tid & 31;
    int rowbase = blockIdx.x * 64;

    // stage W transposed as fp16: sWt[n][k] = (half)W[k][n]
    {
        const float4* W4 = (const float4*)W;
        #pragma unroll
        for (int i = 0; i < 16; ++i) {
            int idx = tid + i * 256;      // [0, 4096)
            int k  = idx >> 5;
            int n4 = idx & 31;
            float4 v = __ldg(&W4[idx]);   // W[k][n4*4 .. n4*4+3]
            sWt[(n4 * 4 + 0) * SH_STR + k] = __float2half_rn(v.x);
            sWt[(n4 * 4 + 1) * SH_STR + k] = __float2half_rn(v.y);
            sWt[(n4 * 4 + 2) * SH_STR + k] = __float2half_rn(v.z);
            sWt[(n4 * 4 + 3) * SH_STR + k] = __float2half_rn(v.w);
        }
    }

    // ---- boundary setup: warp w owns rows [r0, r0+8) ----
    int r0 = rowbase + warp * 8;
    {
        int myc = 0;
        int rr = r0 + lane;
        if (lane < 8 && rr < NN) myc = __ldg(&g_cnt_dst[rr]);
        int sum = myc;
        #pragma unroll
        for (int off = 1; off < 8; off <<= 1) {
            int t = __shfl_up_sync(0xFFFFFFFFu, sum, off);
            if ((lane & 7) >= off) sum += t;
        }
        int beg = (r0 < NN) ? __ldg(&g_rowstart[r0]) : 0;
        if (lane == 0) sBnd[warp][0] = beg;
        if (lane < 8)  sBnd[warp][lane + 1] = beg + sum;
    }
    __syncwarp();

    // ---- linear-stream gather (fp16 features, smem-staged indices) ----
    {
        const uint2* hp = (const uint2*)hin;   // row = 32 uint2 (256 B)
        int beg = sBnd[warp][0];
        int end = sBnd[warp][8];
        int cur = 0;
        int next = sBnd[warp][1];
        float4 acc = make_float4(0.f, 0.f, 0.f, 0.f);
        int* myIdx = sIdx[warp];

        #pragma unroll 1
        for (int cs = beg; cs < end; cs += ICHUNK) {
            int cnt = end - cs;
            if (cnt > ICHUNK) cnt = ICHUNK;
            #pragma unroll
            for (int i = 0; i < 4; ++i) {
                int j = lane + 32 * i;
                if (j < cnt) myIdx[j] = __ldg(&g_csr_src[cs + j]);
            }
            __syncwarp();

            int j = 0;
            uint2 v[8];
            bool pro = (cnt >= 8);
            if (pro) {
                #pragma unroll
                for (int q = 0; q < 8; ++q) {
                    int s = myIdx[q];
                    v[q] = __ldg(&hp[s * 32 + lane]);
                }
            }
            #pragma unroll 1
            for (; j + 16 <= cnt; j += 8) {
                uint2 w[8];
                #pragma unroll
                for (int q = 0; q < 8; ++q) {
                    int s = myIdx[j + 8 + q];
                    w[q] = __ldg(&hp[s * 32 + lane]);
                }
                #pragma unroll
                for (int q = 0; q < 8; ++q) {
                    int ee = cs + j + q;
                    while (ee >= next) {             // warp-uniform
                        flush_row(sA, warp * 8 + cur, lane, acc);
                        acc = make_float4(0.f, 0.f, 0.f, 0.f);
                        ++cur;
                        next = sBnd[warp][cur + 1];
                    }
                    acc_h4(acc, v[q]);
                }
                #pragma unroll
                for (int q = 0; q < 8; ++q) v[q] = w[q];
            }
            if (pro) {
                #pragma unroll
                for (int q = 0; q < 8; ++q) {
                    int ee = cs + j + q;
                    while (ee >= next) {
                        flush_row(sA, warp * 8 + cur, lane, acc);
                        acc = make_float4(0.f, 0.f, 0.f, 0.f);
                        ++cur;
                        next = sBnd[warp][cur + 1];
                    }
                    acc_h4(acc, v[q]);
                }
                j += 8;
            }
            {   // remainder (< 8 edges)
                uint2 rv[8]; int have = cnt - j;
                #pragma unroll
                for (int q = 0; q < 8; ++q) {
                    if (q < have) {
                        int s = myIdx[j + q];
                        rv[q] = __ldg(&hp[s * 32 + lane]);
                    }
                }
                #pragma unroll
                for (int q = 0; q < 8; ++q) {
                    if (q < have) {
                        int ee = cs + j + q;
                        while (ee >= next) {
                            flush_row(sA, warp * 8 + cur, lane, acc);
                            acc = make_float4(0.f, 0.f, 0.f, 0.f);
                            ++cur;
                            next = sBnd[warp][cur + 1];
                        }
                        acc_h4(acc, rv[q]);
                    }
                }
            }
            __syncwarp();   // protect myIdx before next chunk overwrites
        }
        // flush current row and zero-fill remaining rows
        #pragma unroll
        for (int rr = 0; rr < 8; ++rr) {
            if (rr >= cur) {
                flush_row(sA, warp * 8 + rr, lane, acc);
                acc = make_float4(0.f, 0.f, 0.f, 0.f);
            }
        }
    }
    __syncthreads();

    // ---- fp16 tensor-core GEMM: D[64x128] = sA @ W  (m16n8k16, fp32 accum) ----
    int g = lane >> 2;        // 0..7
    int t = lane & 3;         // 0..3
    int rtbase = (warp & 3) * 16;
    int chbase = (warp >> 2) * 64;

    float c[8][4];
    #pragma unroll
    for (int n = 0; n < 8; ++n)
        #pragma unroll
        for (int j = 0; j < 4; ++j) c[n][j] = 0.f;

    const __half* sAr0 = sA + (rtbase + g) * SH_STR;
    const __half* sAr1 = sA + (rtbase + g + 8) * SH_STR;
    #pragma unroll
    for (int k = 0; k < 8; ++k) {
        int k0 = k * 16;
        uint32_t a0 = *(const uint32_t*)(sAr0 + k0 + t * 2);
        uint32_t a1 = *(const uint32_t*)(sAr1 + k0 + t * 2);
        uint32_t a2 = *(const uint32_t*)(sAr0 + k0 + 8 + t * 2);
        uint32_t a3 = *(const uint32_t*)(sAr1 + k0 + 8 + t * 2);
        #pragma unroll
        for (int n = 0; n < 8; ++n) {
            int ncol = chbase + n * 8 + g;
            uint32_t b0 = *(const uint32_t*)(sWt + ncol * SH_STR + k0 + t * 2);
            uint32_t b1 = *(const uint32_t*)(sWt + ncol * SH_STR + k0 + 8 + t * 2);
            mma_f16(c[n], a0, a1, a2, a3, b0, b1);
        }
    }

    // ---- epilogue ----
    int row0 = rowbase + rtbase + g;
    int row1 = row0 + 8;
    float nd0 = 0.f, nd1 = 0.f, ns0 = 1.f, ns1 = 1.f;
    if (row0 < NN) { nd0 = __ldg(&g_norm_dst[row0]); if (PRESCALE) ns0 = __ldg(&g_norm_src[row0]); }
    if (row1 < NN) { nd1 = __ldg(&g_norm_dst[row1]); if (PRESCALE) ns1 = __ldg(&g_norm_src[row1]); }

    if (!LNORM) {
        #pragma unroll
        for (int n = 0; n < 8; ++n) {
            int col = chbase + n * 8 + t * 2;
            float2 bv = *(const float2*)(bias + col);
            if (row0 < NN) {
                float ox = c[n][0] * nd0 + bv.x;
                float oy = c[n][1] * nd0 + bv.y;
                if (GELU) { ox = gelu_exact(ox); oy = gelu_exact(oy); }
                if (PRESCALE) { ox *= ns0; oy *= ns0; }
                ((__half2*)outh)[row0 * 64 + (col >> 1)] = __floats2half2_rn(ox, oy);
            }
            if (row1 < NN) {
                float ox = c[n][2] * nd1 + bv.x;
                float oy = c[n][3] * nd1 + bv.y;
                if (GELU) { ox = gelu_exact(ox); oy = gelu_exact(oy); }
                if (PRESCALE) { ox *= ns1; oy *= ns1; }
                ((__half2*)outh)[row1 * 64 + (col >> 1)] = __floats2half2_rn(ox, oy);
            }
        }
    } else {
        float s0 = 0.f, q0 = 0.f, s1 = 0.f, q1 = 0.f;
        #pragma unroll
        for (int n = 0; n < 8; ++n) {
            int col = chbase + n * 8 + t * 2;
            float2 bv = *(const float2*)(bias + col);
            float h00 = c[n][0] * nd0 + bv.x;
            float h01 = c[n][1] * nd0 + bv.y;
            float h10 = c[n][2] * nd1 + bv.x;
            float h11 = c[n][3] * nd1 + bv.y;
            c[n][0] = h00; c[n][1] = h01; c[n][2] = h10; c[n][3] = h11;
            s0 += h00 + h01; q0 += h00 * h00 + h01 * h01;
            s1 += h10 + h11; q1 += h10 * h10 + h11 * h11;
        }
        __syncthreads();
        float2* sLN = (float2*)sA;          // [64][8] overlay (4 KB < sA)
        int slot = (warp >> 2) * 4 + t;
        sLN[(rtbase + g) * 8 + slot]     = make_float2(s0, q0);
        sLN[(rtbase + g + 8) * 8 + slot] = make_float2(s1, q1);
        __syncthreads();
        float ts0 = 0.f, tq0 = 0.f, ts1 = 0.f, tq1 = 0.f;
        #pragma unroll
        for (int k = 0; k < 8; ++k) {
            float2 p0 = sLN[(rtbase + g) * 8 + k];
            float2 p1 = sLN[(rtbase + g + 8) * 8 + k];
            ts0 += p0.x; tq0 += p0.y;
            ts1 += p1.x; tq1 += p1.y;
        }
        float mu0 = ts0 * (1.0f / FD);
        float mu1 = ts1 * (1.0f / FD);
        float inv0 = rsqrtf(fmaxf(tq0 * (1.0f / FD) - mu0 * mu0, 0.f) + 1e-5f);
        float inv1 = rsqrtf(fmaxf(tq1 * (1.0f / FD) - mu1 * mu1, 0.f) + 1e-5f);
        #pragma unroll
        for (int n = 0; n < 8; ++n) {
            int col = chbase + n * 8 + t * 2;
            float2 gv = *(const float2*)(gamma + col);
            float2 bt = *(const float2*)(beta + col);
            if (row0 < NN) {
                float ox = (c[n][0] - mu0) * inv0 * gv.x + bt.x;
                float oy = (c[n][1] - mu0) * inv0 * gv.y + bt.y;
                *(float2*)(outf + (size_t)row0 * FD + col) = make_float2(ox, oy);
            }
            if (row1 < NN) {
                float ox = (c[n][2] - mu1) * inv1 * gv.x + bt.x;
                float oy = (c[n][3] - mu1) * inv1 * gv.y + bt.y;
                *(float2*)(outf + (size_t)row1 * FD + col) = make_float2(ox, oy);
            }
        }
    }
}

// ---------------- launch ----------------
extern "C" void kernel_launch(void* const* d_in, const int* in_sizes, int n_in,
                              void* d_out, int out_size)
{
    const float* x     = (const float*)d_in[0];
    const int*   src   = (const int*)  d_in[1];
    const int*   dst   = (const int*)  d_in[2];
    const float* Ws[4] = { (const float*)d_in[3], (const float*)d_in[5],
                           (const float*)d_in[7], (const float*)d_in[9] };
    const float* bs[4] = { (const float*)d_in[4], (const float*)d_in[6],
                           (const float*)d_in[8], (const float*)d_in[10] };
    const float* gamma = (const float*)d_in[11];
    const float* beta  = (const float*)d_in[12];
    float* out = (float*)d_out;

    __half *h0, *h1;
    cudaGetSymbolAddress((void**)&h0, g_hh0);
    cudaGetSymbolAddress((void**)&h1, g_hh1);

    cudaFuncSetAttribute(gcn_fused_kernel<true, true, false>,
                         cudaFuncAttributeMaxDynamicSharedMemorySize, SMEM_BYTES);
    cudaFuncSetAttribute(gcn_fused_kernel<false, false, true>,
                         cudaFuncAttributeMaxDynamicSharedMemorySize, SMEM_BYTES);

    const int T = 256;
    zero_counts_kernel<<<(NN + T - 1) / T, T>>>();
    count_deg_kernel<<<(NE + T - 1) / T, T>>>(src, dst);
    make_norm_kernel<<<(NN + T - 1) / T, T>>>();
    scan_block_kernel<<<SCAN_B, SCAN_T>>>();
    scan_bsums_kernel<<<1, 128>>>();
    add_offsets_kernel<<<(NN + T - 1) / T, T>>>();
    fill_csr_kernel<<<(NE + T - 1) / T, T>>>(src, dst);

    // x * norm_src -> fp16 h0
    convert_x_kernel<<<(NN * FD4 + T - 1) / T, T>>>(x, h0);

    const int gemm_blocks = (NN + 63) / 64;
    gcn_fused_kernel<true, true, false><<<gemm_blocks, T, SMEM_BYTES>>>(
        h0, Ws[0], bs[0], h1, nullptr, nullptr, nullptr);
    gcn_fused_kernel<true, true, false><<<gemm_blocks, T, SMEM_BYTES>>>(
        h1, Ws[1], bs[1], h0, nullptr, nullptr, nullptr);
    gcn_fused_kernel<true, true, false><<<gemm_blocks, T, SMEM_BYTES>>>(
        h0, Ws[2], bs[2], h1, nullptr, nullptr, nullptr);
    gcn_fused_kernel<false, false, true><<<gemm_blocks, T, SMEM_BYTES>>>(
        h1, Ws[3], bs[3], nullptr, out, gamma, beta);
}

// round 13
// speedup vs baseline: 1.4805x; 1.0847x over previous
#include <cuda_runtime.h>
#include <cuda_fp16.h>
#include <math.h>
#include <stdint.h>

#define NN 100000
#define NE 1600000
#define FD 128
#define FD4 (FD/4)
#define SCAN_T 1024
#define SCAN_B ((NN + SCAN_T - 1) / SCAN_T)   // 98

// fp16 smem strides (in halves): pad so MMA fragment loads are conflict-free
#define SH_STR 136                    // 272 B per row; word idx = 4g+t unique
#define SMEM_BYTES ((128*SH_STR + 64*SH_STR) * 2)   // 52,224 B
#define ICHUNK 128   // staged indices per warp per chunk

// ---------------- static device scratch ----------------
__device__ __half g_hh0[(size_t)NN * FD];   // fp16 activations (ping)
__device__ __half g_hh1[(size_t)NN * FD];   // fp16 activations (pong)
__device__ int   g_cnt_src[NN];
__device__ int   g_cnt_dst[NN];
__device__ float g_norm_src[NN];
__device__ float g_norm_dst[NN];
__device__ int   g_rowstart[NN];
__device__ int   g_fill[NN];
__device__ int   g_bsum[SCAN_B];
__device__ int   g_boff[SCAN_B];
__device__ int   g_csr_src[NE];

// ---------------- setup kernels ----------------
__global__ void zero_counts_kernel() {
    int i = blockIdx.x * blockDim.x + threadIdx.x;
    if (i < NN) { g_cnt_src[i] = 0; g_cnt_dst[i] = 0; }
}

__global__ void count_deg_kernel(const int* __restrict__ src,
                                 const int* __restrict__ dst) {
    int i = blockIdx.x * blockDim.x + threadIdx.x;
    if (i < NE) {
        atomicAdd(&g_cnt_src[src[i]], 1);
        atomicAdd(&g_cnt_dst[dst[i]], 1);
    }
}

__global__ void __launch_bounds__(SCAN_T) scan_block_kernel() {
    __shared__ int s[SCAN_T];
    int t = threadIdx.x;
    int i = blockIdx.x * SCAN_T + t;
    int v = (i < NN) ? g_cnt_dst[i] : 0;
    s[t] = v;
    __syncthreads();
    #pragma unroll
    for (int off = 1; off < SCAN_T; off <<= 1) {
        int x = (t >= off) ? s[t - off] : 0;
        __syncthreads();
        s[t] += x;
        __syncthreads();
    }
    if (i < NN) g_rowstart[i] = s[t] - v;
    if (t == SCAN_T - 1) g_bsum[blockIdx.x] = s[t];
}

__global__ void scan_bsums_kernel() {
    __shared__ int s[128];
    int t = threadIdx.x;
    int v = (t < SCAN_B) ? g_bsum[t] : 0;
    s[t] = v;
    __syncthreads();
    #pragma unroll
    for (int off = 1; off < 128; off <<= 1) {
        int x = (t >= off) ? s[t - off] : 0;
        __syncthreads();
        s[t] += x;
        __syncthreads();
    }
    if (t < SCAN_B) g_boff[t] = s[t] - v;
}

// add scan offsets + compute degree norms (fused)
__global__ void add_offsets_kernel() {
    int i = blockIdx.x * blockDim.x + threadIdx.x;
    if (i < NN) {
        int v = g_rowstart[i] + g_boff[i >> 10];
        g_rowstart[i] = v;
        g_fill[i] = v;
        g_norm_src[i] = rsqrtf(fmaxf((float)g_cnt_src[i], 1.0f));
        g_norm_dst[i] = rsqrtf(fmaxf((float)g_cnt_dst[i], 1.0f));
    }
}

__global__ void fill_csr_kernel(const int* __restrict__ src,
                                const int* __restrict__ dst) {
    int e = blockIdx.x * blockDim.x + threadIdx.x;
    if (e < NE) {
        int pos = atomicAdd(&g_fill[dst[e]], 1);
        g_csr_src[pos] = src[e];
    }
}

// convert x*norm_src -> fp16
__global__ void convert_x_kernel(const float* __restrict__ x, __half* __restrict__ o) {
    int i = blockIdx.x * blockDim.x + threadIdx.x;
    if (i < NN * FD4) {
        int row = i >> 5;
        float ns = __ldg(&g_norm_src[row]);
        float4 v = __ldg(&((const float4*)x)[i]);
        __half2 a = __floats2half2_rn(v.x * ns, v.y * ns);
        __half2 b = __floats2half2_rn(v.z * ns, v.w * ns);
        uint2 packed;
        packed.x = *(uint32_t*)&a;
        packed.y = *(uint32_t*)&b;
        ((uint2*)o)[i] = packed;
    }
}

// ---------------- helpers ----------------
__device__ __forceinline__ void mma_f16(float* c,
    uint32_t a0, uint32_t a1, uint32_t a2, uint32_t a3,
    uint32_t b0, uint32_t b1)
{
    asm volatile(
        "mma.sync.aligned.m16n8k16.row.col.f32.f16.f16.f32 "
        "{%0,%1,%2,%3}, {%4,%5,%6,%7}, {%8,%9}, {%0,%1,%2,%3};"
        : "+f"(c[0]), "+f"(c[1]), "+f"(c[2]), "+f"(c[3])
        : "r"(a0), "r"(a1), "r"(a2), "r"(a3), "r"(b0), "r"(b1));
}

__device__ __forceinline__ float gelu_exact(float x) {
    return 0.5f * x * (1.0f + erff(x * 0.7071067811865476f));
}

__device__ __forceinline__ void acc_h4(float4& acc, uint2 raw) {
    __half2 ha = *(__half2*)&raw.x;
    __half2 hb = *(__half2*)&raw.y;
    float2 fa = __half22float2(ha);
    float2 fb = __half22float2(hb);
    acc.x += fa.x; acc.y += fa.y; acc.z += fb.x; acc.w += fb.y;
}

// flush fp32 accumulator to fp16 sA row (4 halves per lane)
__device__ __forceinline__ void flush_row(__half* sA, int row, int lane, float4 acc) {
    __half2 a = __floats2half2_rn(acc.x, acc.y);
    __half2 b = __floats2half2_rn(acc.z, acc.w);
    uint2 p;
    p.x = *(uint32_t*)&a;
    p.y = *(uint32_t*)&b;
    *(uint2*)(sA + row * SH_STR + lane * 4) = p;
}

// ---------------- fused gather + fp16 tensor-core GEMM + epilogue ----------------
// Block: 256 threads (8 warps), 64 output rows x 128 cols, 3 blocks/SM.
// Gather: per-warp contiguous CSR range; smem-staged indices; fp16 features,
//         fp32 accumulation, flushed to fp16 sA.
// GEMM: mma.m16n8k16 f16 (fp32 accum), W transposed fp16 in smem.
template <bool GELU, bool PRESCALE, bool LNORM>
__global__ void __launch_bounds__(256, 3) gcn_fused_kernel(
    const __half* __restrict__ hin,   // [NN, FD] fp16, already *norm_src
    const float* __restrict__ W,      // [FD, FD] row-major (k, n)
    const float* __restrict__ bias,   // [FD]
    __half* __restrict__ outh,        // fp16 out (L1-L3)
    float* __restrict__ outf,         // fp32 out (L4)
    const float* __restrict__ gamma,
    const float* __restrict__ beta)
{
    extern __shared__ __half smh[];
    __half* sWt = smh;                    // [128 n][SH_STR k] transposed W
    __half* sA  = smh + 128 * SH_STR;     // [64 row][SH_STR k]
    __shared__ int sBnd[8][9];            // per-warp row boundaries
    __shared__ int sIdx[8][ICHUNK];       // staged edge indices
    int tid  = threadIdx.x;
    int warp = tid >> 5;
    int lane = tid & 31;
    int rowbase = blockIdx.x * 64;

    // stage W transposed as fp16: sWt[n][k] = (half)W[k][n]
    {
        const float4* W4 = (const float4*)W;
        #pragma unroll
        for (int i = 0; i < 16; ++i) {
            int idx = tid + i * 256;      // [0, 4096)
            int k  = idx >> 5;
            int n4 = idx & 31;
            float4 v = __ldg(&W4[idx]);   // W[k][n4*4 .. n4*4+3]
            sWt[(n4 * 4 + 0) * SH_STR + k] = __float2half_rn(v.x);
            sWt[(n4 * 4 + 1) * SH_STR + k] = __float2half_rn(v.y);
            sWt[(n4 * 4 + 2) * SH_STR + k] = __float2half_rn(v.z);
            sWt[(n4 * 4 + 3) * SH_STR + k] = __float2half_rn(v.w);
        }
    }

    // ---- boundary setup: warp w owns rows [r0, r0+8) ----
    int r0 = rowbase + warp * 8;
    {
        int myc = 0;
        int rr = r0 + lane;
        if (lane < 8 && rr < NN) myc = __ldg(&g_cnt_dst[rr]);
        int sum = myc;
        #pragma unroll
        for (int off = 1; off < 8; off <<= 1) {
            int t = __shfl_up_sync(0xFFFFFFFFu, sum, off);
            if ((lane & 7) >= off) sum += t;
        }
        int beg = (r0 < NN) ? __ldg(&g_rowstart[r0]) : 0;
        if (lane == 0) sBnd[warp][0] = beg;
        if (lane < 8)  sBnd[warp][lane + 1] = beg + sum;
    }
    __syncwarp();

    // ---- linear-stream gather (fp16 features, smem-staged indices) ----
    {
        const uint2* hp = (const uint2*)hin;   // row = 32 uint2 (256 B)
        int beg = sBnd[warp][0];
        int end = sBnd[warp][8];
        int cur = 0;
        int next = sBnd[warp][1];
        float4 acc = make_float4(0.f, 0.f, 0.f, 0.f);
        int* myIdx = sIdx[warp];

        #pragma unroll 1
        for (int cs = beg; cs < end; cs += ICHUNK) {
            int cnt = end - cs;
            if (cnt > ICHUNK) cnt = ICHUNK;
            #pragma unroll
            for (int i = 0; i < 4; ++i) {
                int j = lane + 32 * i;
                if (j < cnt) myIdx[j] = __ldg(&g_csr_src[cs + j]);
            }
            __syncwarp();

            int j = 0;
            uint2 v[8];
            bool pro = (cnt >= 8);
            if (pro) {
                #pragma unroll
                for (int q = 0; q < 8; ++q) {
                    int s = myIdx[q];
                    v[q] = __ldg(&hp[s * 32 + lane]);
                }
            }
            #pragma unroll 1
            for (; j + 16 <= cnt; j += 8) {
                uint2 w[8];
                #pragma unroll
                for (int q = 0; q < 8; ++q) {
                    int s = myIdx[j + 8 + q];
                    w[q] = __ldg(&hp[s * 32 + lane]);
                }
                #pragma unroll
                for (int q = 0; q < 8; ++q) {
                    int ee = cs + j + q;
                    while (ee >= next) {             // warp-uniform
                        flush_row(sA, warp * 8 + cur, lane, acc);
                        acc = make_float4(0.f, 0.f, 0.f, 0.f);
                        ++cur;
                        next = sBnd[warp][cur + 1];
                    }
                    acc_h4(acc, v[q]);
                }
                #pragma unroll
                for (int q = 0; q < 8; ++q) v[q] = w[q];
            }
            if (pro) {
                #pragma unroll
                for (int q = 0; q < 8; ++q) {
                    int ee = cs + j + q;
                    while (ee >= next) {
                        flush_row(sA, warp * 8 + cur, lane, acc);
                        acc = make_float4(0.f, 0.f, 0.f, 0.f);
                        ++cur;
                        next = sBnd[warp][cur + 1];
                    }
                    acc_h4(acc, v[q]);
                }
                j += 8;
            }
            {   // remainder (< 8 edges)
                uint2 rv[8]; int have = cnt - j;
                #pragma unroll
                for (int q = 0; q < 8; ++q) {
                    if (q < have) {
                        int s = myIdx[j + q];
                        rv[q] = __ldg(&hp[s * 32 + lane]);
                    }
                }
                #pragma unroll
                for (int q = 0; q < 8; ++q) {
                    if (q < have) {
                        int ee = cs + j + q;
                        while (ee >= next) {
                            flush_row(sA, warp * 8 + cur, lane, acc);
                            acc = make_float4(0.f, 0.f, 0.f, 0.f);
                            ++cur;
                            next = sBnd[warp][cur + 1];
                        }
                        acc_h4(acc, rv[q]);
                    }
                }
            }
            __syncwarp();   // protect myIdx before next chunk overwrites
        }
        // flush current row and zero-fill remaining rows
        #pragma unroll
        for (int rr = 0; rr < 8; ++rr) {
            if (rr >= cur) {
                flush_row(sA, warp * 8 + rr, lane, acc);
                acc = make_float4(0.f, 0.f, 0.f, 0.f);
            }
        }
    }
    __syncthreads();

    // ---- fp16 tensor-core GEMM: D[64x128] = sA @ W  (m16n8k16, fp32 accum) ----
    int g = lane >> 2;        // 0..7
    int t = lane & 3;         // 0..3
    int rtbase = (warp & 3) * 16;
    int chbase = (warp >> 2) * 64;

    float c[8][4];
    #pragma unroll
    for (int n = 0; n < 8; ++n)
        #pragma unroll
        for (int j = 0; j < 4; ++j) c[n][j] = 0.f;

    const __half* sAr0 = sA + (rtbase + g) * SH_STR;
    const __half* sAr1 = sA + (rtbase + g + 8) * SH_STR;
    #pragma unroll
    for (int k = 0; k < 8; ++k) {
        int k0 = k * 16;
        uint32_t a0 = *(const uint32_t*)(sAr0 + k0 + t * 2);
        uint32_t a1 = *(const uint32_t*)(sAr1 + k0 + t * 2);
        uint32_t a2 = *(const uint32_t*)(sAr0 + k0 + 8 + t * 2);
        uint32_t a3 = *(const uint32_t*)(sAr1 + k0 + 8 + t * 2);
        #pragma unroll
        for (int n = 0; n < 8; ++n) {
            int ncol = chbase + n * 8 + g;
            uint32_t b0 = *(const uint32_t*)(sWt + ncol * SH_STR + k0 + t * 2);
            uint32_t b1 = *(const uint32_t*)(sWt + ncol * SH_STR + k0 + 8 + t * 2);
            mma_f16(c[n], a0, a1, a2, a3, b0, b1);
        }
    }

    // ---- epilogue ----
    int row0 = rowbase + rtbase + g;
    int row1 = row0 + 8;
    float nd0 = 0.f, nd1 = 0.f, ns0 = 1.f, ns1 = 1.f;
    if (row0 < NN) { nd0 = __ldg(&g_norm_dst[row0]); if (PRESCALE) ns0 = __ldg(&g_norm_src[row0]); }
    if (row1 < NN) { nd1 = __ldg(&g_norm_dst[row1]); if (PRESCALE) ns1 = __ldg(&g_norm_src[row1]); }

    if (!LNORM) {
        #pragma unroll
        for (int n = 0; n < 8; ++n) {
            int col = chbase + n * 8 + t * 2;
            float2 bv = *(const float2*)(bias + col);
            if (row0 < NN) {
                float ox = c[n][0] * nd0 + bv.x;
                float oy = c[n][1] * nd0 + bv.y;
                if (GELU) { ox = gelu_exact(ox); oy = gelu_exact(oy); }
                if (PRESCALE) { ox *= ns0; oy *= ns0; }
                ((__half2*)outh)[row0 * 64 + (col >> 1)] = __floats2half2_rn(ox, oy);
            }
            if (row1 < NN) {
                float ox = c[n][2] * nd1 + bv.x;
                float oy = c[n][3] * nd1 + bv.y;
                if (GELU) { ox = gelu_exact(ox); oy = gelu_exact(oy); }
                if (PRESCALE) { ox *= ns1; oy *= ns1; }
                ((__half2*)outh)[row1 * 64 + (col >> 1)] = __floats2half2_rn(ox, oy);
            }
        }
    } else {
        float s0 = 0.f, q0 = 0.f, s1 = 0.f, q1 = 0.f;
        #pragma unroll
        for (int n = 0; n < 8; ++n) {
            int col = chbase + n * 8 + t * 2;
            float2 bv = *(const float2*)(bias + col);
            float h00 = c[n][0] * nd0 + bv.x;
            float h01 = c[n][1] * nd0 + bv.y;
            float h10 = c[n][2] * nd1 + bv.x;
            float h11 = c[n][3] * nd1 + bv.y;
            c[n][0] = h00; c[n][1] = h01; c[n][2] = h10; c[n][3] = h11;
            s0 += h00 + h01; q0 += h00 * h00 + h01 * h01;
            s1 += h10 + h11; q1 += h10 * h10 + h11 * h11;
        }
        __syncthreads();
        float2* sLN = (float2*)sA;          // [64][8] overlay (4 KB < sA)
        int slot = (warp >> 2) * 4 + t;
        sLN[(rtbase + g) * 8 + slot]     = make_float2(s0, q0);
        sLN[(rtbase + g + 8) * 8 + slot] = make_float2(s1, q1);
        __syncthreads();
        float ts0 = 0.f, tq0 = 0.f, ts1 = 0.f, tq1 = 0.f;
        #pragma unroll
        for (int k = 0; k < 8; ++k) {
            float2 p0 = sLN[(rtbase + g) * 8 + k];
            float2 p1 = sLN[(rtbase + g + 8) * 8 + k];
            ts0 += p0.x; tq0 += p0.y;
            ts1 += p1.x; tq1 += p1.y;
        }
        float mu0 = ts0 * (1.0f / FD);
        float mu1 = ts1 * (1.0f / FD);
        float inv0 = rsqrtf(fmaxf(tq0 * (1.0f / FD) - mu0 * mu0, 0.f) + 1e-5f);
        float inv1 = rsqrtf(fmaxf(tq1 * (1.0f / FD) - mu1 * mu1, 0.f) + 1e-5f);
        #pragma unroll
        for (int n = 0; n < 8; ++n) {
            int col = chbase + n * 8 + t * 2;
            float2 gv = *(const float2*)(gamma + col);
            float2 bt = *(const float2*)(beta + col);
            if (row0 < NN) {
                float ox = (c[n][0] - mu0) * inv0 * gv.x + bt.x;
                float oy = (c[n][1] - mu0) * inv0 * gv.y + bt.y;
                *(float2*)(outf + (size_t)row0 * FD + col) = make_float2(ox, oy);
            }
            if (row1 < NN) {
                float ox = (c[n][2] - mu1) * inv1 * gv.x + bt.x;
                float oy = (c[n][3] - mu1) * inv1 * gv.y + bt.y;
                *(float2*)(outf + (size_t)row1 * FD + col) = make_float2(ox, oy);
            }
        }
    }
}

// ---------------- launch ----------------
extern "C" void kernel_launch(void* const* d_in, const int* in_sizes, int n_in,
                              void* d_out, int out_size)
{
    const float* x     = (const float*)d_in[0];
    const int*   src   = (const int*)  d_in[1];
    const int*   dst   = (const int*)  d_in[2];
    const float* Ws[4] = { (const float*)d_in[3], (const float*)d_in[5],
                           (const float*)d_in[7], (const float*)d_in[9] };
    const float* bs[4] = { (const float*)d_in[4], (const float*)d_in[6],
                           (const float*)d_in[8], (const float*)d_in[10] };
    const float* gamma = (const float*)d_in[11];
    const float* beta  = (const float*)d_in[12];
    float* out = (float*)d_out;

    __half *h0, *h1;
    cudaGetSymbolAddress((void**)&h0, g_hh0);
    cudaGetSymbolAddress((void**)&h1, g_hh1);

    cudaFuncSetAttribute(gcn_fused_kernel<true, true, false>,
                         cudaFuncAttributeMaxDynamicSharedMemorySize, SMEM_BYTES);
    cudaFuncSetAttribute(gcn_fused_kernel<false, false, true>,
                         cudaFuncAttributeMaxDynamicSharedMemorySize, SMEM_BYTES);

    const int T = 256;
    zero_counts_kernel<<<(NN + T - 1) / T, T>>>();
    count_deg_kernel<<<(NE + T - 1) / T, T>>>(src, dst);
    scan_block_kernel<<<SCAN_B, SCAN_T>>>();
    scan_bsums_kernel<<<1, 128>>>();
    add_offsets_kernel<<<(NN + T - 1) / T, T>>>();   // also computes norms
    fill_csr_kernel<<<(NE + T - 1) / T, T>>>(src, dst);

    // x * norm_src -> fp16 h0
    convert_x_kernel<<<(NN * FD4 + T - 1) / T, T>>>(x, h0);

    const int gemm_blocks = (NN + 63) / 64;
    gcn_fused_kernel<true, true, false><<<gemm_blocks, T, SMEM_BYTES>>>(
        h0, Ws[0], bs[0], h1, nullptr, nullptr, nullptr);
    gcn_fused_kernel<true, true, false><<<gemm_blocks, T, SMEM_BYTES>>>(
        h1, Ws[1], bs[1], h0, nullptr, nullptr, nullptr);
    gcn_fused_kernel<true, true, false><<<gemm_blocks, T, SMEM_BYTES>>>(
        h0, Ws[2], bs[2], h1, nullptr, nullptr, nullptr);
    gcn_fused_kernel<false, false, true><<<gemm_blocks, T, SMEM_BYTES>>>(
        h1, Ws[3], bs[3], nullptr, out, gamma, beta);
}

// round 14
// speedup vs baseline: 2.0691x; 1.3976x over previous
#include <cuda_runtime.h>
#include <cuda_fp16.h>
#include <math.h>
#include <stdint.h>

#define NN 100000
#define NE 1600000
#define FD 128
#define FD4 (FD/4)
#define SCAN_T 1024
#define SCAN_B ((NN + SCAN_T - 1) / SCAN_T)   // 98

// fp16 smem strides (in halves): pad so MMA fragment loads are conflict-free
#define SH_STR 136                    // 272 B per row; word idx = 4g+t unique
#define SMEM_BYTES ((128*SH_STR + 64*SH_STR) * 2)   // 52,224 B
#define ICHUNK 128   // staged indices per warp per chunk
#define W_U4 ((128 * SH_STR * 2) / 16)   // 2176 uint4 per staged W

// ---------------- static device scratch ----------------
__device__ __half g_hh0[(size_t)NN * FD];   // fp16 activations (ping)
__device__ __half g_hh1[(size_t)NN * FD];   // fp16 activations (pong)
__device__ __half g_wh[4][128 * SH_STR];    // preconverted transposed fp16 W
__device__ int   g_cnt_src[NN];
__device__ int   g_cnt_dst[NN];
__device__ float g_norm_src[NN];
__device__ float g_norm_dst[NN];
__device__ int   g_rowstart[NN];
__device__ int   g_fill[NN];
__device__ int   g_bsum[SCAN_B];
__device__ int   g_boff[SCAN_B];
__device__ int   g_csr_src[NE];

// ---------------- setup kernels ----------------
__global__ void zero_counts_kernel() {
    int i = blockIdx.x * blockDim.x + threadIdx.x;
    if (i < NN) { g_cnt_src[i] = 0; g_cnt_dst[i] = 0; }
}

// 4 edges per thread via int4
__global__ void count_deg_kernel(const int* __restrict__ src,
                                 const int* __restrict__ dst) {
    int i = blockIdx.x * blockDim.x + threadIdx.x;
    if (i < NE / 4) {
        int4 s4 = __ldg(&((const int4*)src)[i]);
        int4 d4 = __ldg(&((const int4*)dst)[i]);
        atomicAdd(&g_cnt_src[s4.x], 1); atomicAdd(&g_cnt_dst[d4.x], 1);
        atomicAdd(&g_cnt_src[s4.y], 1); atomicAdd(&g_cnt_dst[d4.y], 1);
        atomicAdd(&g_cnt_src[s4.z], 1); atomicAdd(&g_cnt_dst[d4.z], 1);
        atomicAdd(&g_cnt_src[s4.w], 1); atomicAdd(&g_cnt_dst[d4.w], 1);
    }
}

__global__ void __launch_bounds__(SCAN_T) scan_block_kernel() {
    __shared__ int s[SCAN_T];
    int t = threadIdx.x;
    int i = blockIdx.x * SCAN_T + t;
    int v = (i < NN) ? g_cnt_dst[i] : 0;
    s[t] = v;
    __syncthreads();
    #pragma unroll
    for (int off = 1; off < SCAN_T; off <<= 1) {
        int x = (t >= off) ? s[t - off] : 0;
        __syncthreads();
        s[t] += x;
        __syncthreads();
    }
    if (i < NN) g_rowstart[i] = s[t] - v;
    if (t == SCAN_T - 1) g_bsum[blockIdx.x] = s[t];
}

__global__ void scan_bsums_kernel() {
    __shared__ int s[128];
    int t = threadIdx.x;
    int v = (t < SCAN_B) ? g_bsum[t] : 0;
    s[t] = v;
    __syncthreads();
    #pragma unroll
    for (int off = 1; off < 128; off <<= 1) {
        int x = (t >= off) ? s[t - off] : 0;
        __syncthreads();
        s[t] += x;
        __syncthreads();
    }
    if (t < SCAN_B) g_boff[t] = s[t] - v;
}

// add scan offsets + compute degree norms (fused)
__global__ void add_offsets_kernel() {
    int i = blockIdx.x * blockDim.x + threadIdx.x;
    if (i < NN) {
        int v = g_rowstart[i] + g_boff[i >> 10];
        g_rowstart[i] = v;
        g_fill[i] = v;
        g_norm_src[i] = rsqrtf(fmaxf((float)g_cnt_src[i], 1.0f));
        g_norm_dst[i] = rsqrtf(fmaxf((float)g_cnt_dst[i], 1.0f));
    }
}

// 4 edges per thread via int4
__global__ void fill_csr_kernel(const int* __restrict__ src,
                                const int* __restrict__ dst) {
    int i = blockIdx.x * blockDim.x + threadIdx.x;
    if (i < NE / 4) {
        int4 s4 = __ldg(&((const int4*)src)[i]);
        int4 d4 = __ldg(&((const int4*)dst)[i]);
        g_csr_src[atomicAdd(&g_fill[d4.x], 1)] = s4.x;
        g_csr_src[atomicAdd(&g_fill[d4.y], 1)] = s4.y;
        g_csr_src[atomicAdd(&g_fill[d4.z], 1)] = s4.z;
        g_csr_src[atomicAdd(&g_fill[d4.w], 1)] = s4.w;
    }
}

// convert x*norm_src -> fp16
__global__ void convert_x_kernel(const float* __restrict__ x, __half* __restrict__ o) {
    int i = blockIdx.x * blockDim.x + threadIdx.x;
    if (i < NN * FD4) {
        int row = i >> 5;
        float ns = __ldg(&g_norm_src[row]);
        float4 v = __ldg(&((const float4*)x)[i]);
        __half2 a = __floats2half2_rn(v.x * ns, v.y * ns);
        __half2 b = __floats2half2_rn(v.z * ns, v.w * ns);
        uint2 packed;
        packed.x = *(uint32_t*)&a;
        packed.y = *(uint32_t*)&b;
        ((uint2*)o)[i] = packed;
    }
}

// pre-convert W [k][n] fp32 -> transposed padded fp16 [n][SH_STR k]
__global__ void convert_w_kernel(const float* __restrict__ W, __half* __restrict__ o) {
    int idx = blockIdx.x * blockDim.x + threadIdx.x;
    if (idx < FD * FD) {
        int n = idx >> 7;
        int k = idx & 127;
        o[n * SH_STR + k] = __float2half_rn(__ldg(&W[k * FD + n]));
    }
}

// ---------------- helpers ----------------
__device__ __forceinline__ void mma_f16(float* c,
    uint32_t a0, uint32_t a1, uint32_t a2, uint32_t a3,
    uint32_t b0, uint32_t b1)
{
    asm volatile(
        "mma.sync.aligned.m16n8k16.row.col.f32.f16.f16.f32 "
        "{%0,%1,%2,%3}, {%4,%5,%6,%7}, {%8,%9}, {%0,%1,%2,%3};"
        : "+f"(c[0]), "+f"(c[1]), "+f"(c[2]), "+f"(c[3])
        : "r"(a0), "r"(a1), "r"(a2), "r"(a3), "r"(b0), "r"(b1));
}

__device__ __forceinline__ float gelu_exact(float x) {
    return 0.5f * x * (1.0f + erff(x * 0.7071067811865476f));
}

__device__ __forceinline__ void acc_h4(float4& acc, uint2 raw) {
    __half2 ha = *(__half2*)&raw.x;
    __half2 hb = *(__half2*)&raw.y;
    float2 fa = __half22float2(ha);
    float2 fb = __half22float2(hb);
    acc.x += fa.x; acc.y += fa.y; acc.z += fb.x; acc.w += fb.y;
}

// flush fp32 accumulator to fp16 sA row (4 halves per lane)
__device__ __forceinline__ void flush_row(__half* sA, int row, int lane, float4 acc) {
    __half2 a = __floats2half2_rn(acc.x, acc.y);
    __half2 b = __floats2half2_rn(acc.z, acc.w);
    uint2 p;
    p.x = *(uint32_t*)&a;
    p.y = *(uint32_t*)&b;
    *(uint2*)(sA + row * SH_STR + lane * 4) = p;
}

// ---------------- fused gather + fp16 tensor-core GEMM + epilogue ----------------
// Block: 256 threads (8 warps), 64 output rows x 128 cols, 3 blocks/SM.
// Gather: per-warp contiguous CSR range; smem-staged indices; fp16 features,
//         fp32 accumulation, flushed to fp16 sA.
// GEMM: mma.m16n8k16 f16 (fp32 accum), preconverted fp16 W staged by uint4 copy.
template <bool GELU, bool PRESCALE, bool LNORM>
__global__ void __launch_bounds__(256, 3) gcn_fused_kernel(
    const __half* __restrict__ hin,   // [NN, FD] fp16, already *norm_src
    const __half* __restrict__ Wh,    // [128][SH_STR] transposed fp16 W
    const float* __restrict__ bias,   // [FD]
    __half* __restrict__ outh,        // fp16 out (L1-L3)
    float* __restrict__ outf,         // fp32 out (L4)
    const float* __restrict__ gamma,
    const float* __restrict__ beta)
{
    extern __shared__ __half smh[];
    __half* sWt = smh;                    // [128 n][SH_STR k] transposed W
    __half* sA  = smh + 128 * SH_STR;     // [64 row][SH_STR k]
    __shared__ int sBnd[8][9];            // per-warp row boundaries
    __shared__ int sIdx[8][ICHUNK];       // staged edge indices
    int tid  = threadIdx.x;
    int warp = tid >> 5;
    int lane = tid & 31;
    int rowbase = blockIdx.x * 64;

    // stage W: straight uint4 copy of preconverted layout
    {
        const uint4* Wg = (const uint4*)Wh;
        uint4* sW4 = (uint4*)sWt;
        #pragma unroll
        for (int i = 0; i < 9; ++i) {
            int idx = tid + i * 256;
            if (idx < W_U4) sW4[idx] = __ldg(&Wg[idx]);
        }
    }

    // ---- boundary setup: warp w owns rows [r0, r0+8) ----
    int r0 = rowbase + warp * 8;
    {
        int myc = 0;
        int rr = r0 + lane;
        if (lane < 8 && rr < NN) myc = __ldg(&g_cnt_dst[rr]);
        int sum = myc;
        #pragma unroll
        for (int off = 1; off < 8; off <<= 1) {
            int t = __shfl_up_sync(0xFFFFFFFFu, sum, off);
            if ((lane & 7) >= off) sum += t;
        }
        int beg = (r0 < NN) ? __ldg(&g_rowstart[r0]) : 0;
        if (lane == 0) sBnd[warp][0] = beg;
        if (lane < 8)  sBnd[warp][lane + 1] = beg + sum;
    }
    __syncwarp();

    // ---- linear-stream gather (fp16 features, smem-staged indices) ----
    {
        const uint2* hp = (const uint2*)hin;   // row = 32 uint2 (256 B)
        int beg = sBnd[warp][0];
        int end = sBnd[warp][8];
        int cur = 0;
        int next = sBnd[warp][1];
        float4 acc = make_float4(0.f, 0.f, 0.f, 0.f);
        int* myIdx = sIdx[warp];

        #pragma unroll 1
        for (int cs = beg; cs < end; cs += ICHUNK) {
            int cnt = end - cs;
            if (cnt > ICHUNK) cnt = ICHUNK;
            #pragma unroll
            for (int i = 0; i < 4; ++i) {
                int j = lane + 32 * i;
                if (j < cnt) myIdx[j] = __ldg(&g_csr_src[cs + j]);
            }
            __syncwarp();

            int j = 0;
            uint2 v[8];
            bool pro = (cnt >= 8);
            if (pro) {
                #pragma unroll
                for (int q = 0; q < 8; ++q) {
                    int s = myIdx[q];
                    v[q] = __ldg(&hp[s * 32 + lane]);
                }
            }
            #pragma unroll 1
            for (; j + 16 <= cnt; j += 8) {
                uint2 w[8];
                #pragma unroll
                for (int q = 0; q < 8; ++q) {
                    int s = myIdx[j + 8 + q];
                    w[q] = __ldg(&hp[s * 32 + lane]);
                }
                #pragma unroll
                for (int q = 0; q < 8; ++q) {
                    int ee = cs + j + q;
                    while (ee >= next) {             // warp-uniform
                        flush_row(sA, warp * 8 + cur, lane, acc);
                        acc = make_float4(0.f, 0.f, 0.f, 0.f);
                        ++cur;
                        next = sBnd[warp][cur + 1];
                    }
                    acc_h4(acc, v[q]);
                }
                #pragma unroll
                for (int q = 0; q < 8; ++q) v[q] = w[q];
            }
            if (pro) {
                #pragma unroll
                for (int q = 0; q < 8; ++q) {
                    int ee = cs + j + q;
                    while (ee >= next) {
                        flush_row(sA, warp * 8 + cur, lane, acc);
                        acc = make_float4(0.f, 0.f, 0.f, 0.f);
                        ++cur;
                        next = sBnd[warp][cur + 1];
                    }
                    acc_h4(acc, v[q]);
                }
                j += 8;
            }
            {   // remainder (< 8 edges)
                uint2 rv[8]; int have = cnt - j;
                #pragma unroll
                for (int q = 0; q < 8; ++q) {
                    if (q < have) {
                        int s = myIdx[j + q];
                        rv[q] = __ldg(&hp[s * 32 + lane]);
                    }
                }
                #pragma unroll
                for (int q = 0; q < 8; ++q) {
                    if (q < have) {
                        int ee = cs + j + q;
                        while (ee >= next) {
                            flush_row(sA, warp * 8 + cur, lane, acc);
                            acc = make_float4(0.f, 0.f, 0.f, 0.f);
                            ++cur;
                            next = sBnd[warp][cur + 1];
                        }
                        acc_h4(acc, rv[q]);
                    }
                }
            }
            __syncwarp();   // protect myIdx before next chunk overwrites
        }
        // flush current row and zero-fill remaining rows
        #pragma unroll
        for (int rr = 0; rr < 8; ++rr) {
            if (rr >= cur) {
                flush_row(sA, warp * 8 + rr, lane, acc);
                acc = make_float4(0.f, 0.f, 0.f, 0.f);
            }
        }
    }
    __syncthreads();

    // ---- fp16 tensor-core GEMM: D[64x128] = sA @ W  (m16n8k16, fp32 accum) ----
    int g = lane >> 2;        // 0..7
    int t = lane & 3;         // 0..3
    int rtbase = (warp & 3) * 16;
    int chbase = (warp >> 2) * 64;

    float c[8][4];
    #pragma unroll
    for (int n = 0; n < 8; ++n)
        #pragma unroll
        for (int j = 0; j < 4; ++j) c[n][j] = 0.f;

    const __half* sAr0 = sA + (rtbase + g) * SH_STR;
    const __half* sAr1 = sA + (rtbase + g + 8) * SH_STR;
    #pragma unroll
    for (int k = 0; k < 8; ++k) {
        int k0 = k * 16;
        uint32_t a0 = *(const uint32_t*)(sAr0 + k0 + t * 2);
        uint32_t a1 = *(const uint32_t*)(sAr1 + k0 + t * 2);
        uint32_t a2 = *(const uint32_t*)(sAr0 + k0 + 8 + t * 2);
        uint32_t a3 = *(const uint32_t*)(sAr1 + k0 + 8 + t * 2);
        #pragma unroll
        for (int n = 0; n < 8; ++n) {
            int ncol = chbase + n * 8 + g;
            uint32_t b0 = *(const uint32_t*)(sWt + ncol * SH_STR + k0 + t * 2);
            uint32_t b1 = *(const uint32_t*)(sWt + ncol * SH_STR + k0 + 8 + t * 2);
            mma_f16(c[n], a0, a1, a2, a3, b0, b1);
        }
    }

    // ---- epilogue ----
    int row0 = rowbase + rtbase + g;
    int row1 = row0 + 8;
    float nd0 = 0.f, nd1 = 0.f, ns0 = 1.f, ns1 = 1.f;
    if (row0 < NN) { nd0 = __ldg(&g_norm_dst[row0]); if (PRESCALE) ns0 = __ldg(&g_norm_src[row0]); }
    if (row1 < NN) { nd1 = __ldg(&g_norm_dst[row1]); if (PRESCALE) ns1 = __ldg(&g_norm_src[row1]); }

    if (!LNORM) {
        #pragma unroll
        for (int n = 0; n < 8; ++n) {
            int col = chbase + n * 8 + t * 2;
            float2 bv = *(const float2*)(bias + col);
            if (row0 < NN) {
                float ox = c[n][0] * nd0 + bv.x;
                float oy = c[n][1] * nd0 + bv.y;
                if (GELU) { ox = gelu_exact(ox); oy = gelu_exact(oy); }
                if (PRESCALE) { ox *= ns0; oy *= ns0; }
                ((__half2*)outh)[row0 * 64 + (col >> 1)] = __floats2half2_rn(ox, oy);
            }
            if (row1 < NN) {
                float ox = c[n][2] * nd1 + bv.x;
                float oy = c[n][3] * nd1 + bv.y;
                if (GELU) { ox = gelu_exact(ox); oy = gelu_exact(oy); }
                if (PRESCALE) { ox *= ns1; oy *= ns1; }
                ((__half2*)outh)[row1 * 64 + (col >> 1)] = __floats2half2_rn(ox, oy);
            }
        }
    } else {
        float s0 = 0.f, q0 = 0.f, s1 = 0.f, q1 = 0.f;
        #pragma unroll
        for (int n = 0; n < 8; ++n) {
            int col = chbase + n * 8 + t * 2;
            float2 bv = *(const float2*)(bias + col);
            float h00 = c[n][0] * nd0 + bv.x;
            float h01 = c[n][1] * nd0 + bv.y;
            float h10 = c[n][2] * nd1 + bv.x;
            float h11 = c[n][3] * nd1 + bv.y;
            c[n][0] = h00; c[n][1] = h01; c[n][2] = h10; c[n][3] = h11;
            s0 += h00 + h01; q0 += h00 * h00 + h01 * h01;
            s1 += h10 + h11; q1 += h10 * h10 + h11 * h11;
        }
        __syncthreads();
        float2* sLN = (float2*)sA;          // [64][8] overlay (4 KB < sA)
        int slot = (warp >> 2) * 4 + t;
        sLN[(rtbase + g) * 8 + slot]     = make_float2(s0, q0);
        sLN[(rtbase + g + 8) * 8 + slot] = make_float2(s1, q1);
        __syncthreads();
        float ts0 = 0.f, tq0 = 0.f, ts1 = 0.f, tq1 = 0.f;
        #pragma unroll
        for (int k = 0; k < 8; ++k) {
            float2 p0 = sLN[(rtbase + g) * 8 + k];
            float2 p1 = sLN[(rtbase + g + 8) * 8 + k];
            ts0 += p0.x; tq0 += p0.y;
            ts1 += p1.x; tq1 += p1.y;
        }
        float mu0 = ts0 * (1.0f / FD);
        float mu1 = ts1 * (1.0f / FD);
        float inv0 = rsqrtf(fmaxf(tq0 * (1.0f / FD) - mu0 * mu0, 0.f) + 1e-5f);
        float inv1 = rsqrtf(fmaxf(tq1 * (1.0f / FD) - mu1 * mu1, 0.f) + 1e-5f);
        #pragma unroll
        for (int n = 0; n < 8; ++n) {
            int col = chbase + n * 8 + t * 2;
            float2 gv = *(const float2*)(gamma + col);
            float2 bt = *(const float2*)(beta + col);
            if (row0 < NN) {
                float ox = (c[n][0] - mu0) * inv0 * gv.x + bt.x;
                float oy = (c[n][1] - mu0) * inv0 * gv.y + bt.y;
                *(float2*)(outf + (size_t)row0 * FD + col) = make_float2(ox, oy);
            }
            if (row1 < NN) {
                float ox = (c[n][2] - mu1) * inv1 * gv.x + bt.x;
                float oy = (c[n][3] - mu1) * inv1 * gv.y + bt.y;
                *(float2*)(outf + (size_t)row1 * FD + col) = make_float2(ox, oy);
            }
        }
    }
}

// ---------------- launch ----------------
extern "C" void kernel_launch(void* const* d_in, const int* in_sizes, int n_in,
                              void* d_out, int out_size)
{
    const float* x     = (const float*)d_in[0];
    const int*   src   = (const int*)  d_in[1];
    const int*   dst   = (const int*)  d_in[2];
    const float* Ws[4] = { (const float*)d_in[3], (const float*)d_in[5],
                           (const float*)d_in[7], (const float*)d_in[9] };
    const float* bs[4] = { (const float*)d_in[4], (const float*)d_in[6],
                           (const float*)d_in[8], (const float*)d_in[10] };
    const float* gamma = (const float*)d_in[11];
    const float* beta  = (const float*)d_in[12];
    float* out = (float*)d_out;

    __half *h0, *h1, *wh;
    cudaGetSymbolAddress((void**)&h0, g_hh0);
    cudaGetSymbolAddress((void**)&h1, g_hh1);
    cudaGetSymbolAddress((void**)&wh, g_wh);

    cudaFuncSetAttribute(gcn_fused_kernel<true, true, false>,
                         cudaFuncAttributeMaxDynamicSharedMemorySize, SMEM_BYTES);
    cudaFuncSetAttribute(gcn_fused_kernel<false, false, true>,
                         cudaFuncAttributeMaxDynamicSharedMemorySize, SMEM_BYTES);

    const int T = 256;
    zero_counts_kernel<<<(NN + T - 1) / T, T>>>();
    count_deg_kernel<<<(NE / 4 + T - 1) / T, T>>>(src, dst);
    scan_block_kernel<<<SCAN_B, SCAN_T>>>();
    scan_bsums_kernel<<<1, 128>>>();
    add_offsets_kernel<<<(NN + T - 1) / T, T>>>();   // also computes norms
    fill_csr_kernel<<<(NE / 4 + T - 1) / T, T>>>(src, dst);

    // preconvert weights (transposed fp16) + x*norm_src -> fp16 h0
    const int wblocks = (FD * FD + T - 1) / T;
    for (int L = 0; L < 4; ++L)
        convert_w_kernel<<<wblocks, T>>>(Ws[L], wh + (size_t)L * 128 * SH_STR);
    convert_x_kernel<<<(NN * FD4 + T - 1) / T, T>>>(x, h0);

    const int gemm_blocks = (NN + 63) / 64;
    gcn_fused_kernel<true, true, false><<<gemm_blocks, T, SMEM_BYTES>>>(
        h0, wh + 0 * 128 * SH_STR, bs[0], h1, nullptr, nullptr, nullptr);
    gcn_fused_kernel<true, true, false><<<gemm_blocks, T, SMEM_BYTES>>>(
        h1, wh + 1 * 128 * SH_STR, bs[1], h0, nullptr, nullptr, nullptr);
    gcn_fused_kernel<true, true, false><<<gemm_blocks, T, SMEM_BYTES>>>(
        h0, wh + 2 * 128 * SH_STR, bs[2], h1, nullptr, nullptr, nullptr);
    gcn_fused_kernel<false, false, true><<<gemm_blocks, T, SMEM_BYTES>>>(
        h1, wh + 3 * 128 * SH_STR, bs[3], nullptr, out, gamma, beta);
}

// round 15
// speedup vs baseline: 2.0947x; 1.0124x over previous
#include <cuda_runtime.h>
#include <cuda_fp16.h>
#include <math.h>
#include <stdint.h>

#define NN 100000
#define NE 1600000
#define FD 128
#define FD4 (FD/4)
#define SCAN_T 1024
#define SCAN_B ((NN + SCAN_T - 1) / SCAN_T)   // 98

// fp16 smem strides (in halves): pad so MMA fragment loads are conflict-free
#define SH_STR 136                    // 272 B per row; word idx = 4g+t unique
#define SMEM_BYTES ((128*SH_STR + 64*SH_STR) * 2)   // 52,224 B
#define ICHUNK 128   // staged indices per warp per chunk
#define W_U4 ((128 * SH_STR * 2) / 16)   // 2176 uint4 per staged W

// ---------------- static device scratch ----------------
__device__ __half g_hh0[(size_t)NN * FD];   // fp16 activations (ping)
__device__ __half g_hh1[(size_t)NN * FD];   // fp16 activations (pong)
__device__ __half g_wh[4][128 * SH_STR];    // preconverted transposed fp16 W
__device__ int   g_cnt_src[NN];
__device__ int   g_cnt_dst[NN];
__device__ float g_norm_src[NN];
__device__ float g_norm_dst[NN];
__device__ int   g_rowstart[NN];
__device__ int   g_fill[NN];
__device__ int   g_total;
__device__ int   g_csr_src[NE];

// ---------------- setup kernels ----------------
__global__ void zero_counts_kernel() {
    int i = blockIdx.x * blockDim.x + threadIdx.x;
    if (i < NN) { g_cnt_src[i] = 0; g_cnt_dst[i] = 0; }
    if (i == 0) g_total = 0;
}

// 4 edges per thread via int4
__global__ void count_deg_kernel(const int* __restrict__ src,
                                 const int* __restrict__ dst) {
    int i = blockIdx.x * blockDim.x + threadIdx.x;
    if (i < NE / 4) {
        int4 s4 = __ldg(&((const int4*)src)[i]);
        int4 d4 = __ldg(&((const int4*)dst)[i]);
        atomicAdd(&g_cnt_src[s4.x], 1); atomicAdd(&g_cnt_dst[d4.x], 1);
        atomicAdd(&g_cnt_src[s4.y], 1); atomicAdd(&g_cnt_dst[d4.y], 1);
        atomicAdd(&g_cnt_src[s4.z], 1); atomicAdd(&g_cnt_dst[d4.z], 1);
        atomicAdd(&g_cnt_src[s4.w], 1); atomicAdd(&g_cnt_dst[d4.w], 1);
    }
}

// single-pass scan: block-local exclusive scan + atomic block base.
// Any block-base order yields a valid CSR (row ranges stay contiguous, and
// 8-row warp groups never span a 1024-node scan block). Also emits fill + norms.
__global__ void __launch_bounds__(SCAN_T) scan_fused_kernel() {
    __shared__ int s[SCAN_T];
    __shared__ int base_sh;
    int t = threadIdx.x;
    int i = blockIdx.x * SCAN_T + t;
    int v = (i < NN) ? g_cnt_dst[i] : 0;
    s[t] = v;
    __syncthreads();
    #pragma unroll
    for (int off = 1; off < SCAN_T; off <<= 1) {
        int x = (t >= off) ? s[t - off] : 0;
        __syncthreads();
        s[t] += x;
        __syncthreads();
    }
    if (t == SCAN_T - 1) base_sh = atomicAdd(&g_total, s[t]);
    __syncthreads();
    if (i < NN) {
        int rs = base_sh + s[t] - v;
        g_rowstart[i] = rs;
        g_fill[i] = rs;
        g_norm_src[i] = rsqrtf(fmaxf((float)g_cnt_src[i], 1.0f));
        g_norm_dst[i] = rsqrtf(fmaxf((float)g_cnt_dst[i], 1.0f));
    }
}

// 4 edges per thread via int4
__global__ void fill_csr_kernel(const int* __restrict__ src,
                                const int* __restrict__ dst) {
    int i = blockIdx.x * blockDim.x + threadIdx.x;
    if (i < NE / 4) {
        int4 s4 = __ldg(&((const int4*)src)[i]);
        int4 d4 = __ldg(&((const int4*)dst)[i]);
        g_csr_src[atomicAdd(&g_fill[d4.x], 1)] = s4.x;
        g_csr_src[atomicAdd(&g_fill[d4.y], 1)] = s4.y;
        g_csr_src[atomicAdd(&g_fill[d4.z], 1)] = s4.z;
        g_csr_src[atomicAdd(&g_fill[d4.w], 1)] = s4.w;
    }
}

// convert x*norm_src -> fp16
__global__ void convert_x_kernel(const float* __restrict__ x, __half* __restrict__ o) {
    int i = blockIdx.x * blockDim.x + threadIdx.x;
    if (i < NN * FD4) {
        int row = i >> 5;
        float ns = __ldg(&g_norm_src[row]);
        float4 v = __ldg(&((const float4*)x)[i]);
        __half2 a = __floats2half2_rn(v.x * ns, v.y * ns);
        __half2 b = __floats2half2_rn(v.z * ns, v.w * ns);
        uint2 packed;
        packed.x = *(uint32_t*)&a;
        packed.y = *(uint32_t*)&b;
        ((uint2*)o)[i] = packed;
    }
}

// pre-convert all 4 W [k][n] fp32 -> transposed padded fp16 [n][SH_STR k]
__global__ void convert_w_all_kernel(const float* __restrict__ W0,
                                     const float* __restrict__ W1,
                                     const float* __restrict__ W2,
                                     const float* __restrict__ W3,
                                     __half* __restrict__ o) {
    int idx = blockIdx.x * blockDim.x + threadIdx.x;
    if (idx < 4 * FD * FD) {
        int L = idx >> 14;
        int r = idx & (FD * FD - 1);
        int n = r >> 7;
        int k = r & 127;
        const float* W = (L == 0) ? W0 : (L == 1) ? W1 : (L == 2) ? W2 : W3;
        o[(size_t)L * 128 * SH_STR + n * SH_STR + k] =
            __float2half_rn(__ldg(&W[k * FD + n]));
    }
}

// ---------------- helpers ----------------
__device__ __forceinline__ void mma_f16(float* c,
    uint32_t a0, uint32_t a1, uint32_t a2, uint32_t a3,
    uint32_t b0, uint32_t b1)
{
    asm volatile(
        "mma.sync.aligned.m16n8k16.row.col.f32.f16.f16.f32 "
        "{%0,%1,%2,%3}, {%4,%5,%6,%7}, {%8,%9}, {%0,%1,%2,%3};"
        : "+f"(c[0]), "+f"(c[1]), "+f"(c[2]), "+f"(c[3])
        : "r"(a0), "r"(a1), "r"(a2), "r"(a3), "r"(b0), "r"(b1));
}

__device__ __forceinline__ float gelu_exact(float x) {
    return 0.5f * x * (1.0f + erff(x * 0.7071067811865476f));
}

__device__ __forceinline__ void acc_h4(float4& acc, uint2 raw) {
    __half2 ha = *(__half2*)&raw.x;
    __half2 hb = *(__half2*)&raw.y;
    float2 fa = __half22float2(ha);
    float2 fb = __half22float2(hb);
    acc.x += fa.x; acc.y += fa.y; acc.z += fb.x; acc.w += fb.y;
}

// flush fp32 accumulator to fp16 sA row (4 halves per lane)
__device__ __forceinline__ void flush_row(__half* sA, int row, int lane, float4 acc) {
    __half2 a = __floats2half2_rn(acc.x, acc.y);
    __half2 b = __floats2half2_rn(acc.z, acc.w);
    uint2 p;
    p.x = *(uint32_t*)&a;
    p.y = *(uint32_t*)&b;
    *(uint2*)(sA + row * SH_STR + lane * 4) = p;
}

// ---------------- fused gather + fp16 tensor-core GEMM + epilogue ----------------
// Block: 256 threads (8 warps), 64 output rows x 128 cols, 4 blocks/SM.
// Gather: per-warp contiguous CSR range; smem-staged indices; fp16 features,
//         fp32 accumulation, flushed to fp16 sA.
// GEMM: mma.m16n8k16 f16 (fp32 accum), preconverted fp16 W staged by uint4 copy.
template <bool GELU, bool PRESCALE, bool LNORM>
__global__ void __launch_bounds__(256, 4) gcn_fused_kernel(
    const __half* __restrict__ hin,   // [NN, FD] fp16, already *norm_src
    const __half* __restrict__ Wh,    // [128][SH_STR] transposed fp16 W
    const float* __restrict__ bias,   // [FD]
    __half* __restrict__ outh,        // fp16 out (L1-L3)
    float* __restrict__ outf,         // fp32 out (L4)
    const float* __restrict__ gamma,
    const float* __restrict__ beta)
{
    extern __shared__ __half smh[];
    __half* sWt = smh;                    // [128 n][SH_STR k] transposed W
    __half* sA  = smh + 128 * SH_STR;     // [64 row][SH_STR k]
    __shared__ int sBnd[8][9];            // per-warp row boundaries
    __shared__ int sIdx[8][ICHUNK];       // staged edge indices
    int tid  = threadIdx.x;
    int warp = tid >> 5;
    int lane = tid & 31;
    int rowbase = blockIdx.x * 64;

    // stage W: straight uint4 copy of preconverted layout
    {
        const uint4* Wg = (const uint4*)Wh;
        uint4* sW4 = (uint4*)sWt;
        #pragma unroll
        for (int i = 0; i < 9; ++i) {
            int idx = tid + i * 256;
            if (idx < W_U4) sW4[idx] = __ldg(&Wg[idx]);
        }
    }

    // ---- boundary setup: warp w owns rows [r0, r0+8) ----
    int r0 = rowbase + warp * 8;
    {
        int myc = 0;
        int rr = r0 + lane;
        if (lane < 8 && rr < NN) myc = __ldg(&g_cnt_dst[rr]);
        int sum = myc;
        #pragma unroll
        for (int off = 1; off < 8; off <<= 1) {
            int t = __shfl_up_sync(0xFFFFFFFFu, sum, off);
            if ((lane & 7) >= off) sum += t;
        }
        int beg = (r0 < NN) ? __ldg(&g_rowstart[r0]) : 0;
        if (lane == 0) sBnd[warp][0] = beg;
        if (lane < 8)  sBnd[warp][lane + 1] = beg + sum;
    }
    __syncwarp();

    // ---- linear-stream gather (fp16 features, smem-staged indices) ----
    {
        const uint2* hp = (const uint2*)hin;   // row = 32 uint2 (256 B)
        int beg = sBnd[warp][0];
        int end = sBnd[warp][8];
        int cur = 0;
        int next = sBnd[warp][1];
        float4 acc = make_float4(0.f, 0.f, 0.f, 0.f);
        int* myIdx = sIdx[warp];

        #pragma unroll 1
        for (int cs = beg; cs < end; cs += ICHUNK) {
            int cnt = end - cs;
            if (cnt > ICHUNK) cnt = ICHUNK;
            #pragma unroll
            for (int i = 0; i < 4; ++i) {
                int j = lane + 32 * i;
                if (j < cnt) myIdx[j] = __ldg(&g_csr_src[cs + j]);
            }
            __syncwarp();

            int j = 0;
            uint2 v[8];
            bool pro = (cnt >= 8);
            if (pro) {
                #pragma unroll
                for (int q = 0; q < 8; ++q) {
                    int s = myIdx[q];
                    v[q] = __ldg(&hp[s * 32 + lane]);
                }
            }
            #pragma unroll 1
            for (; j + 16 <= cnt; j += 8) {
                uint2 w[8];
                #pragma unroll
                for (int q = 0; q < 8; ++q) {
                    int s = myIdx[j + 8 + q];
                    w[q] = __ldg(&hp[s * 32 + lane]);
                }
                #pragma unroll
                for (int q = 0; q < 8; ++q) {
                    int ee = cs + j + q;
                    while (ee >= next) {             // warp-uniform
                        flush_row(sA, warp * 8 + cur, lane, acc);
                        acc = make_float4(0.f, 0.f, 0.f, 0.f);
                        ++cur;
                        next = sBnd[warp][cur + 1];
                    }
                    acc_h4(acc, v[q]);
                }
                #pragma unroll
                for (int q = 0; q < 8; ++q) v[q] = w[q];
            }
            if (pro) {
                #pragma unroll
                for (int q = 0; q < 8; ++q) {
                    int ee = cs + j + q;
                    while (ee >= next) {
                        flush_row(sA, warp * 8 + cur, lane, acc);
                        acc = make_float4(0.f, 0.f, 0.f, 0.f);
                        ++cur;
                        next = sBnd[warp][cur + 1];
                    }
                    acc_h4(acc, v[q]);
                }
                j += 8;
            }
            {   // remainder (< 8 edges)
                uint2 rv[8]; int have = cnt - j;
                #pragma unroll
                for (int q = 0; q < 8; ++q) {
                    if (q < have) {
                        int s = myIdx[j + q];
                        rv[q] = __ldg(&hp[s * 32 + lane]);
                    }
                }
                #pragma unroll
                for (int q = 0; q < 8; ++q) {
                    if (q < have) {
                        int ee = cs + j + q;
                        while (ee >= next) {
                            flush_row(sA, warp * 8 + cur, lane, acc);
                            acc = make_float4(0.f, 0.f, 0.f, 0.f);
                            ++cur;
                            next = sBnd[warp][cur + 1];
                        }
                        acc_h4(acc, rv[q]);
                    }
                }
            }
            __syncwarp();   // protect myIdx before next chunk overwrites
        }
        // flush current row and zero-fill remaining rows
        #pragma unroll
        for (int rr = 0; rr < 8; ++rr) {
            if (rr >= cur) {
                flush_row(sA, warp * 8 + rr, lane, acc);
                acc = make_float4(0.f, 0.f, 0.f, 0.f);
            }
        }
    }
    __syncthreads();

    // ---- fp16 tensor-core GEMM: D[64x128] = sA @ W  (m16n8k16, fp32 accum) ----
    int g = lane >> 2;        // 0..7
    int t = lane & 3;         // 0..3
    int rtbase = (warp & 3) * 16;
    int chbase = (warp >> 2) * 64;

    float c[8][4];
    #pragma unroll
    for (int n = 0; n < 8; ++n)
        #pragma unroll
        for (int j = 0; j < 4; ++j) c[n][j] = 0.f;

    const __half* sAr0 = sA + (rtbase + g) * SH_STR;
    const __half* sAr1 = sA + (rtbase + g + 8) * SH_STR;
    #pragma unroll
    for (int k = 0; k < 8; ++k) {
        int k0 = k * 16;
        uint32_t a0 = *(const uint32_t*)(sAr0 + k0 + t * 2);
        uint32_t a1 = *(const uint32_t*)(sAr1 + k0 + t * 2);
        uint32_t a2 = *(const uint32_t*)(sAr0 + k0 + 8 + t * 2);
        uint32_t a3 = *(const uint32_t*)(sAr1 + k0 + 8 + t * 2);
        #pragma unroll
        for (int n = 0; n < 8; ++n) {
            int ncol = chbase + n * 8 + g;
            uint32_t b0 = *(const uint32_t*)(sWt + ncol * SH_STR + k0 + t * 2);
            uint32_t b1 = *(const uint32_t*)(sWt + ncol * SH_STR + k0 + 8 + t * 2);
            mma_f16(c[n], a0, a1, a2, a3, b0, b1);
        }
    }

    // ---- epilogue ----
    int row0 = rowbase + rtbase + g;
    int row1 = row0 + 8;
    float nd0 = 0.f, nd1 = 0.f, ns0 = 1.f, ns1 = 1.f;
    if (row0 < NN) { nd0 = __ldg(&g_norm_dst[row0]); if (PRESCALE) ns0 = __ldg(&g_norm_src[row0]); }
    if (row1 < NN) { nd1 = __ldg(&g_norm_dst[row1]); if (PRESCALE) ns1 = __ldg(&g_norm_src[row1]); }

    if (!LNORM) {
        #pragma unroll
        for (int n = 0; n < 8; ++n) {
            int col = chbase + n * 8 + t * 2;
            float2 bv = *(const float2*)(bias + col);
            if (row0 < NN) {
                float ox = c[n][0] * nd0 + bv.x;
                float oy = c[n][1] * nd0 + bv.y;
                if (GELU) { ox = gelu_exact(ox); oy = gelu_exact(oy); }
                if (PRESCALE) { ox *= ns0; oy *= ns0; }
                ((__half2*)outh)[row0 * 64 + (col >> 1)] = __floats2half2_rn(ox, oy);
            }
            if (row1 < NN) {
                float ox = c[n][2] * nd1 + bv.x;
                float oy = c[n][3] * nd1 + bv.y;
                if (GELU) { ox = gelu_exact(ox); oy = gelu_exact(oy); }
                if (PRESCALE) { ox *= ns1; oy *= ns1; }
                ((__half2*)outh)[row1 * 64 + (col >> 1)] = __floats2half2_rn(ox, oy);
            }
        }
    } else {
        float s0 = 0.f, q0 = 0.f, s1 = 0.f, q1 = 0.f;
        #pragma unroll
        for (int n = 0; n < 8; ++n) {
            int col = chbase + n * 8 + t * 2;
            float2 bv = *(const float2*)(bias + col);
            float h00 = c[n][0] * nd0 + bv.x;
            float h01 = c[n][1] * nd0 + bv.y;
            float h10 = c[n][2] * nd1 + bv.x;
            float h11 = c[n][3] * nd1 + bv.y;
            c[n][0] = h00; c[n][1] = h01; c[n][2] = h10; c[n][3] = h11;
            s0 += h00 + h01; q0 += h00 * h00 + h01 * h01;
            s1 += h10 + h11; q1 += h10 * h10 + h11 * h11;
        }
        __syncthreads();
        float2* sLN = (float2*)sA;          // [64][8] overlay (4 KB < sA)
        int slot = (warp >> 2) * 4 + t;
        sLN[(rtbase + g) * 8 + slot]     = make_float2(s0, q0);
        sLN[(rtbase + g + 8) * 8 + slot] = make_float2(s1, q1);
        __syncthreads();
        float ts0 = 0.f, tq0 = 0.f, ts1 = 0.f, tq1 = 0.f;
        #pragma unroll
        for (int k = 0; k < 8; ++k) {
            float2 p0 = sLN[(rtbase + g) * 8 + k];
            float2 p1 = sLN[(rtbase + g + 8) * 8 + k];
            ts0 += p0.x; tq0 += p0.y;
            ts1 += p1.x; tq1 += p1.y;
        }
        float mu0 = ts0 * (1.0f / FD);
        float mu1 = ts1 * (1.0f / FD);
        float inv0 = rsqrtf(fmaxf(tq0 * (1.0f / FD) - mu0 * mu0, 0.f) + 1e-5f);
        float inv1 = rsqrtf(fmaxf(tq1 * (1.0f / FD) - mu1 * mu1, 0.f) + 1e-5f);
        #pragma unroll
        for (int n = 0; n < 8; ++n) {
            int col = chbase + n * 8 + t * 2;
            float2 gv = *(const float2*)(gamma + col);
            float2 bt = *(const float2*)(beta + col);
            if (row0 < NN) {
                float ox = (c[n][0] - mu0) * inv0 * gv.x + bt.x;
                float oy = (c[n][1] - mu0) * inv0 * gv.y + bt.y;
                *(float2*)(outf + (size_t)row0 * FD + col) = make_float2(ox, oy);
            }
            if (row1 < NN) {
                float ox = (c[n][2] - mu1) * inv1 * gv.x + bt.x;
                float oy = (c[n][3] - mu1) * inv1 * gv.y + bt.y;
                *(float2*)(outf + (size_t)row1 * FD + col) = make_float2(ox, oy);
            }
        }
    }
}

// ---------------- launch ----------------
extern "C" void kernel_launch(void* const* d_in, const int* in_sizes, int n_in,
                              void* d_out, int out_size)
{
    const float* x     = (const float*)d_in[0];
    const int*   src   = (const int*)  d_in[1];
    const int*   dst   = (const int*)  d_in[2];
    const float* Ws[4] = { (const float*)d_in[3], (const float*)d_in[5],
                           (const float*)d_in[7], (const float*)d_in[9] };
    const float* bs[4] = { (const float*)d_in[4], (const float*)d_in[6],
                           (const float*)d_in[8], (const float*)d_in[10] };
    const float* gamma = (const float*)d_in[11];
    const float* beta  = (const float*)d_in[12];
    float* out = (float*)d_out;

    __half *h0, *h1, *wh;
    cudaGetSymbolAddress((void**)&h0, g_hh0);
    cudaGetSymbolAddress((void**)&h1, g_hh1);
    cudaGetSymbolAddress((void**)&wh, g_wh);

    cudaFuncSetAttribute(gcn_fused_kernel<true, true, false>,
                         cudaFuncAttributeMaxDynamicSharedMemorySize, SMEM_BYTES);
    cudaFuncSetAttribute(gcn_fused_kernel<false, false, true>,
                         cudaFuncAttributeMaxDynamicSharedMemorySize, SMEM_BYTES);

    const int T = 256;
    zero_counts_kernel<<<(NN + T - 1) / T, T>>>();
    count_deg_kernel<<<(NE / 4 + T - 1) / T, T>>>(src, dst);
    scan_fused_kernel<<<SCAN_B, SCAN_T>>>();     // scan + fill + norms
    fill_csr_kernel<<<(NE / 4 + T - 1) / T, T>>>(src, dst);

    // preconvert all weights (one launch) + x*norm_src -> fp16 h0
    convert_w_all_kernel<<<(4 * FD * FD + T - 1) / T, T>>>(
        Ws[0], Ws[1], Ws[2], Ws[3], wh);
    convert_x_kernel<<<(NN * FD4 + T - 1) / T, T>>>(x, h0);

    const int gemm_blocks = (NN + 63) / 64;
    gcn_fused_kernel<true, true, false><<<gemm_blocks, T, SMEM_BYTES>>>(
        h0, wh + 0 * 128 * SH_STR, bs[0], h1, nullptr, nullptr, nullptr);
    gcn_fused_kernel<true, true, false><<<gemm_blocks, T, SMEM_BYTES>>>(
        h1, wh + 1 * 128 * SH_STR, bs[1], h0, nullptr, nullptr, nullptr);
    gcn_fused_kernel<true, true, false><<<gemm_blocks, T, SMEM_BYTES>>>(
        h0, wh + 2 * 128 * SH_STR, bs[2], h1, nullptr, nullptr, nullptr);
    gcn_fused_kernel<false, false, true><<<gemm_blocks, T, SMEM_BYTES>>>(
        h1, wh + 3 * 128 * SH_STR, bs[3], nullptr, out, gamma, beta);
}

// round 16
// speedup vs baseline: 2.1494x; 1.0261x over previous
#include <cuda_runtime.h>
#include <cuda_fp16.h>
#include <math.h>
#include <stdint.h>

#define NN 100000
#define NE 1600000
#define FD 128
#define FD4 (FD/4)
#define SCAN_T 1024
#define SCAN_B ((NN + SCAN_T - 1) / SCAN_T)   // 98

// fp16 smem strides (in halves): pad so MMA fragment loads are conflict-free
#define SH_STR 136                    // 272 B per row; word idx = 4g+t unique
#define SMEM_BYTES ((128*SH_STR + 64*SH_STR) * 2)   // 52,224 B
#define ICHUNK 128   // staged indices per warp per chunk
#define W_U4 ((128 * SH_STR * 2) / 16)   // 2176 uint4 per staged W

// ---------------- static device scratch ----------------
__device__ __half g_hh0[(size_t)NN * FD];   // fp16 activations (ping)
__device__ __half g_hh1[(size_t)NN * FD];   // fp16 activations (pong)
__device__ __half g_wh[4][128 * SH_STR];    // preconverted transposed fp16 W
__device__ int   g_cnt_src[NN];
__device__ int   g_cnt_dst[NN];
__device__ float g_norm_src[NN];
__device__ float g_norm_dst[NN];
__device__ int   g_rowstart[NN];
__device__ int   g_fill[NN];
__device__ int   g_total;
__device__ int   g_csr_src[NE];

// ---------------- setup kernels ----------------
// 4 edges per thread via int4
__global__ void count_deg_kernel(const int* __restrict__ src,
                                 const int* __restrict__ dst) {
    int i = blockIdx.x * blockDim.x + threadIdx.x;
    if (i < NE / 4) {
        int4 s4 = __ldg(&((const int4*)src)[i]);
        int4 d4 = __ldg(&((const int4*)dst)[i]);
        atomicAdd(&g_cnt_src[s4.x], 1); atomicAdd(&g_cnt_dst[d4.x], 1);
        atomicAdd(&g_cnt_src[s4.y], 1); atomicAdd(&g_cnt_dst[d4.y], 1);
        atomicAdd(&g_cnt_src[s4.z], 1); atomicAdd(&g_cnt_dst[d4.z], 1);
        atomicAdd(&g_cnt_src[s4.w], 1); atomicAdd(&g_cnt_dst[d4.w], 1);
    }
}

// single-pass scan: block-local exclusive scan + atomic block base.
// Any block-base order yields a valid CSR (row ranges stay contiguous within a
// scan block, and 64-row tiles never span a 1024-node scan block). Also norms.
__global__ void __launch_bounds__(SCAN_T) scan_fused_kernel() {
    __shared__ int s[SCAN_T];
    __shared__ int base_sh;
    int t = threadIdx.x;
    int i = blockIdx.x * SCAN_T + t;
    int v = (i < NN) ? g_cnt_dst[i] : 0;
    s[t] = v;
    __syncthreads();
    #pragma unroll
    for (int off = 1; off < SCAN_T; off <<= 1) {
        int x = (t >= off) ? s[t - off] : 0;
        __syncthreads();
        s[t] += x;
        __syncthreads();
    }
    if (t == SCAN_T - 1) base_sh = atomicAdd(&g_total, s[t]);
    __syncthreads();
    if (i < NN) {
        int rs = base_sh + s[t] - v;
        g_rowstart[i] = rs;
        g_fill[i] = rs;
        g_norm_src[i] = rsqrtf(fmaxf((float)g_cnt_src[i], 1.0f));
        g_norm_dst[i] = rsqrtf(fmaxf((float)g_cnt_dst[i], 1.0f));
    }
}

// 4 edges per thread via int4
__global__ void fill_csr_kernel(const int* __restrict__ src,
                                const int* __restrict__ dst) {
    int i = blockIdx.x * blockDim.x + threadIdx.x;
    if (i < NE / 4) {
        int4 s4 = __ldg(&((const int4*)src)[i]);
        int4 d4 = __ldg(&((const int4*)dst)[i]);
        g_csr_src[atomicAdd(&g_fill[d4.x], 1)] = s4.x;
        g_csr_src[atomicAdd(&g_fill[d4.y], 1)] = s4.y;
        g_csr_src[atomicAdd(&g_fill[d4.z], 1)] = s4.z;
        g_csr_src[atomicAdd(&g_fill[d4.w], 1)] = s4.w;
    }
}

// convert x*norm_src -> fp16
__global__ void convert_x_kernel(const float* __restrict__ x, __half* __restrict__ o) {
    int i = blockIdx.x * blockDim.x + threadIdx.x;
    if (i < NN * FD4) {
        int row = i >> 5;
        float ns = __ldg(&g_norm_src[row]);
        float4 v = __ldg(&((const float4*)x)[i]);
        __half2 a = __floats2half2_rn(v.x * ns, v.y * ns);
        __half2 b = __floats2half2_rn(v.z * ns, v.w * ns);
        uint2 packed;
        packed.x = *(uint32_t*)&a;
        packed.y = *(uint32_t*)&b;
        ((uint2*)o)[i] = packed;
    }
}

// pre-convert all 4 W [k][n] fp32 -> transposed padded fp16 [n][SH_STR k]
__global__ void convert_w_all_kernel(const float* __restrict__ W0,
                                     const float* __restrict__ W1,
                                     const float* __restrict__ W2,
                                     const float* __restrict__ W3,
                                     __half* __restrict__ o) {
    int idx = blockIdx.x * blockDim.x + threadIdx.x;
    if (idx < 4 * FD * FD) {
        int L = idx >> 14;
        int r = idx & (FD * FD - 1);
        int n = r >> 7;
        int k = r & 127;
        const float* W = (L == 0) ? W0 : (L == 1) ? W1 : (L == 2) ? W2 : W3;
        o[(size_t)L * 128 * SH_STR + n * SH_STR + k] =
            __float2half_rn(__ldg(&W[k * FD + n]));
    }
}

// ---------------- helpers ----------------
__device__ __forceinline__ void mma_f16(float* c,
    uint32_t a0, uint32_t a1, uint32_t a2, uint32_t a3,
    uint32_t b0, uint32_t b1)
{
    asm volatile(
        "mma.sync.aligned.m16n8k16.row.col.f32.f16.f16.f32 "
        "{%0,%1,%2,%3}, {%4,%5,%6,%7}, {%8,%9}, {%0,%1,%2,%3};"
        : "+f"(c[0]), "+f"(c[1]), "+f"(c[2]), "+f"(c[3])
        : "r"(a0), "r"(a1), "r"(a2), "r"(a3), "r"(b0), "r"(b1));
}

__device__ __forceinline__ float gelu_exact(float x) {
    return 0.5f * x * (1.0f + erff(x * 0.7071067811865476f));
}

__device__ __forceinline__ void acc_h4(float4& acc, uint2 raw) {
    __half2 ha = *(__half2*)&raw.x;
    __half2 hb = *(__half2*)&raw.y;
    float2 fa = __half22float2(ha);
    float2 fb = __half22float2(hb);
    acc.x += fa.x; acc.y += fa.y; acc.z += fb.x; acc.w += fb.y;
}

// flush fp32 accumulator to fp16 sA row (4 halves per lane)
__device__ __forceinline__ void flush_row(__half* sA, int row, int lane, float4 acc) {
    __half2 a = __floats2half2_rn(acc.x, acc.y);
    __half2 b = __floats2half2_rn(acc.z, acc.w);
    uint2 p;
    p.x = *(uint32_t*)&a;
    p.y = *(uint32_t*)&b;
    *(uint2*)(sA + row * SH_STR + lane * 4) = p;
}

// gather a 4-row slot (rows [r0glob, r0glob+4)) into sA rows [sArow0, +4).
// Rows within a tile are contiguous in the CSR, so boundaries come from
// 5 direct loads — no prefix scan.
__device__ __forceinline__ void gather_slot(
    const uint2* __restrict__ hp, int r0glob, int lane,
    __half* __restrict__ sA, int sArow0, int* __restrict__ myIdx)
{
    int bnd[5];
    bnd[0] = (r0glob < NN) ? __ldg(&g_rowstart[r0glob]) : 0;
    int run = bnd[0];
    #pragma unroll
    for (int i = 0; i < 4; ++i) {
        int rr = r0glob + i;
        int c = (rr < NN) ? __ldg(&g_cnt_dst[rr]) : 0;
        run += c;
        bnd[i + 1] = run;
    }
    int beg = bnd[0], end = bnd[4];
    int cur = 0;
    int next = bnd[1];
    float4 acc = make_float4(0.f, 0.f, 0.f, 0.f);

    #pragma unroll 1
    for (int cs = beg; cs < end; cs += ICHUNK) {
        int cnt = end - cs;
        if (cnt > ICHUNK) cnt = ICHUNK;
        #pragma unroll
        for (int i = 0; i < 4; ++i) {
            int j = lane + 32 * i;
            if (j < cnt) myIdx[j] = __ldg(&g_csr_src[cs + j]);
        }
        __syncwarp();

        int j = 0;
        uint2 v[8];
        bool pro = (cnt >= 8);
        if (pro) {
            #pragma unroll
            for (int q = 0; q < 8; ++q) {
                int s = myIdx[q];
                v[q] = __ldg(&hp[s * 32 + lane]);
            }
        }
        #pragma unroll 1
        for (; j + 16 <= cnt; j += 8) {
            uint2 w[8];
            #pragma unroll
            for (int q = 0; q < 8; ++q) {
                int s = myIdx[j + 8 + q];
                w[q] = __ldg(&hp[s * 32 + lane]);
            }
            #pragma unroll
            for (int q = 0; q < 8; ++q) {
                int ee = cs + j + q;
                while (ee >= next) {                 // warp-uniform
                    flush_row(sA, sArow0 + cur, lane, acc);
                    acc = make_float4(0.f, 0.f, 0.f, 0.f);
                    ++cur;
                    next = bnd[cur + 1];
                }
                acc_h4(acc, v[q]);
            }
            #pragma unroll
            for (int q = 0; q < 8; ++q) v[q] = w[q];
        }
        if (pro) {
            #pragma unroll
            for (int q = 0; q < 8; ++q) {
                int ee = cs + j + q;
                while (ee >= next) {
                    flush_row(sA, sArow0 + cur, lane, acc);
                    acc = make_float4(0.f, 0.f, 0.f, 0.f);
                    ++cur;
                    next = bnd[cur + 1];
                }
                acc_h4(acc, v[q]);
            }
            j += 8;
        }
        {   // remainder (< 8 edges)
            uint2 rv[8]; int have = cnt - j;
            #pragma unroll
            for (int q = 0; q < 8; ++q) {
                if (q < have) {
                    int s = myIdx[j + q];
                    rv[q] = __ldg(&hp[s * 32 + lane]);
                }
            }
            #pragma unroll
            for (int q = 0; q < 8; ++q) {
                if (q < have) {
                    int ee = cs + j + q;
                    while (ee >= next) {
                        flush_row(sA, sArow0 + cur, lane, acc);
                        acc = make_float4(0.f, 0.f, 0.f, 0.f);
                        ++cur;
                        next = bnd[cur + 1];
                    }
                    acc_h4(acc, rv[q]);
                }
            }
        }
        __syncwarp();   // protect myIdx before next chunk overwrites
    }
    // flush current row and zero-fill remaining rows
    #pragma unroll
    for (int rr = 0; rr < 4; ++rr) {
        if (rr >= cur) {
            flush_row(sA, sArow0 + rr, lane, acc);
            acc = make_float4(0.f, 0.f, 0.f, 0.f);
        }
    }
}

// ---------------- fused gather + fp16 tensor-core GEMM + epilogue ----------------
// Block: 256 threads (8 warps), 64 output rows x 128 cols, 4 blocks/SM.
// Gather: 16 slots of 4 rows, warps claim slots via shared counter (block-local
//         work stealing kills intra-block degree-imbalance tail).
// GEMM: mma.m16n8k16 f16 (fp32 accum), preconverted fp16 W staged by uint4 copy.
template <bool GELU, bool PRESCALE, bool LNORM>
__global__ void __launch_bounds__(256, 4) gcn_fused_kernel(
    const __half* __restrict__ hin,   // [NN, FD] fp16, already *norm_src
    const __half* __restrict__ Wh,    // [128][SH_STR] transposed fp16 W
    const float* __restrict__ bias,   // [FD]
    __half* __restrict__ outh,        // fp16 out (L1-L3)
    float* __restrict__ outf,         // fp32 out (L4)
    const float* __restrict__ gamma,
    const float* __restrict__ beta)
{
    extern __shared__ __half smh[];
    __half* sWt = smh;                    // [128 n][SH_STR k] transposed W
    __half* sA  = smh + 128 * SH_STR;     // [64 row][SH_STR k]
    __shared__ int sIdx[8][ICHUNK];       // staged edge indices (per warp)
    __shared__ int sSlot;                 // work-stealing slot counter
    int tid  = threadIdx.x;
    int warp = tid >> 5;
    int lane = tid & 31;
    int rowbase = blockIdx.x * 64;

    if (tid == 0) sSlot = 0;

    // stage W: straight uint4 copy of preconverted layout
    {
        const uint4* Wg = (const uint4*)Wh;
        uint4* sW4 = (uint4*)sWt;
        #pragma unroll
        for (int i = 0; i < 9; ++i) {
            int idx = tid + i * 256;
            if (idx < W_U4) sW4[idx] = __ldg(&Wg[idx]);
        }
    }
    __syncthreads();   // sSlot visible to all warps

    // ---- gather via block-local work stealing over 16 slots x 4 rows ----
    {
        const uint2* hp = (const uint2*)hin;   // row = 32 uint2 (256 B)
        for (;;) {
            int s;
            if (lane == 0) s = atomicAdd(&sSlot, 1);
            s = __shfl_sync(0xFFFFFFFFu, s, 0);
            if (s >= 16) break;
            gather_slot(hp, rowbase + 4 * s, lane, sA, 4 * s, sIdx[warp]);
        }
    }
    __syncthreads();

    // ---- fp16 tensor-core GEMM: D[64x128] = sA @ W  (m16n8k16, fp32 accum) ----
    int g = lane >> 2;        // 0..7
    int t = lane & 3;         // 0..3
    int rtbase = (warp & 3) * 16;
    int chbase = (warp >> 2) * 64;

    float c[8][4];
    #pragma unroll
    for (int n = 0; n < 8; ++n)
        #pragma unroll
        for (int j = 0; j < 4; ++j) c[n][j] = 0.f;

    const __half* sAr0 = sA + (rtbase + g) * SH_STR;
    const __half* sAr1 = sA + (rtbase + g + 8) * SH_STR;
    #pragma unroll
    for (int k = 0; k < 8; ++k) {
        int k0 = k * 16;
        uint32_t a0 = *(const uint32_t*)(sAr0 + k0 + t * 2);
        uint32_t a1 = *(const uint32_t*)(sAr1 + k0 + t * 2);
        uint32_t a2 = *(const uint32_t*)(sAr0 + k0 + 8 + t * 2);
        uint32_t a3 = *(const uint32_t*)(sAr1 + k0 + 8 + t * 2);
        #pragma unroll
        for (int n = 0; n < 8; ++n) {
            int ncol = chbase + n * 8 + g;
            uint32_t b0 = *(const uint32_t*)(sWt + ncol * SH_STR + k0 + t * 2);
            uint32_t b1 = *(const uint32_t*)(sWt + ncol * SH_STR + k0 + 8 + t * 2);
            mma_f16(c[n], a0, a1, a2, a3, b0, b1);
        }
    }

    // ---- epilogue ----
    int row0 = rowbase + rtbase + g;
    int row1 = row0 + 8;
    float nd0 = 0.f, nd1 = 0.f, ns0 = 1.f, ns1 = 1.f;
    if (row0 < NN) { nd0 = __ldg(&g_norm_dst[row0]); if (PRESCALE) ns0 = __ldg(&g_norm_src[row0]); }
    if (row1 < NN) { nd1 = __ldg(&g_norm_dst[row1]); if (PRESCALE) ns1 = __ldg(&g_norm_src[row1]); }

    if (!LNORM) {
        #pragma unroll
        for (int n = 0; n < 8; ++n) {
            int col = chbase + n * 8 + t * 2;
            float2 bv = *(const float2*)(bias + col);
            if (row0 < NN) {
                float ox = c[n][0] * nd0 + bv.x;
                float oy = c[n][1] * nd0 + bv.y;
                if (GELU) { ox = gelu_exact(ox); oy = gelu_exact(oy); }
                if (PRESCALE) { ox *= ns0; oy *= ns0; }
                ((__half2*)outh)[row0 * 64 + (col >> 1)] = __floats2half2_rn(ox, oy);
            }
            if (row1 < NN) {
                float ox = c[n][2] * nd1 + bv.x;
                float oy = c[n][3] * nd1 + bv.y;
                if (GELU) { ox = gelu_exact(ox); oy = gelu_exact(oy); }
                if (PRESCALE) { ox *= ns1; oy *= ns1; }
                ((__half2*)outh)[row1 * 64 + (col >> 1)] = __floats2half2_rn(ox, oy);
            }
        }
    } else {
        float s0 = 0.f, q0 = 0.f, s1 = 0.f, q1 = 0.f;
        #pragma unroll
        for (int n = 0; n < 8; ++n) {
            int col = chbase + n * 8 + t * 2;
            float2 bv = *(const float2*)(bias + col);
            float h00 = c[n][0] * nd0 + bv.x;
            float h01 = c[n][1] * nd0 + bv.y;
            float h10 = c[n][2] * nd1 + bv.x;
            float h11 = c[n][3] * nd1 + bv.y;
            c[n][0] = h00; c[n][1] = h01; c[n][2] = h10; c[n][3] = h11;
            s0 += h00 + h01; q0 += h00 * h00 + h01 * h01;
            s1 += h10 + h11; q1 += h10 * h10 + h11 * h11;
        }
        __syncthreads();
        float2* sLN = (float2*)sA;          // [64][8] overlay (4 KB < sA)
        int slot = (warp >> 2) * 4 + t;
        sLN[(rtbase + g) * 8 + slot]     = make_float2(s0, q0);
        sLN[(rtbase + g + 8) * 8 + slot] = make_float2(s1, q1);
        __syncthreads();
        float ts0 = 0.f, tq0 = 0.f, ts1 = 0.f, tq1 = 0.f;
        #pragma unroll
        for (int k = 0; k < 8; ++k) {
            float2 p0 = sLN[(rtbase + g) * 8 + k];
            float2 p1 = sLN[(rtbase + g + 8) * 8 + k];
            ts0 += p0.x; tq0 += p0.y;
            ts1 += p1.x; tq1 += p1.y;
        }
        float mu0 = ts0 * (1.0f / FD);
        float mu1 = ts1 * (1.0f / FD);
        float inv0 = rsqrtf(fmaxf(tq0 * (1.0f / FD) - mu0 * mu0, 0.f) + 1e-5f);
        float inv1 = rsqrtf(fmaxf(tq1 * (1.0f / FD) - mu1 * mu1, 0.f) + 1e-5f);
        #pragma unroll
        for (int n = 0; n < 8; ++n) {
            int col = chbase + n * 8 + t * 2;
            float2 gv = *(const float2*)(gamma + col);
            float2 bt = *(const float2*)(beta + col);
            if (row0 < NN) {
                float ox = (c[n][0] - mu0) * inv0 * gv.x + bt.x;
                float oy = (c[n][1] - mu0) * inv0 * gv.y + bt.y;
                *(float2*)(outf + (size_t)row0 * FD + col) = make_float2(ox, oy);
            }
            if (row1 < NN) {
                float ox = (c[n][2] - mu1) * inv1 * gv.x + bt.x;
                float oy = (c[n][3] - mu1) * inv1 * gv.y + bt.y;
                *(float2*)(outf + (size_t)row1 * FD + col) = make_float2(ox, oy);
            }
        }
    }
}

// ---------------- launch ----------------
extern "C" void kernel_launch(void* const* d_in, const int* in_sizes, int n_in,
                              void* d_out, int out_size)
{
    const float* x     = (const float*)d_in[0];
    const int*   src   = (const int*)  d_in[1];
    const int*   dst   = (const int*)  d_in[2];
    const float* Ws[4] = { (const float*)d_in[3], (const float*)d_in[5],
                           (const float*)d_in[7], (const float*)d_in[9] };
    const float* bs[4] = { (const float*)d_in[4], (const float*)d_in[6],
                           (const float*)d_in[8], (const float*)d_in[10] };
    const float* gamma = (const float*)d_in[11];
    const float* beta  = (const float*)d_in[12];
    float* out = (float*)d_out;

    __half *h0, *h1, *wh;
    int *cnt_src_p, *cnt_dst_p, *total_p;
    cudaGetSymbolAddress((void**)&h0, g_hh0);
    cudaGetSymbolAddress((void**)&h1, g_hh1);
    cudaGetSymbolAddress((void**)&wh, g_wh);
    cudaGetSymbolAddress((void**)&cnt_src_p, g_cnt_src);
    cudaGetSymbolAddress((void**)&cnt_dst_p, g_cnt_dst);
    cudaGetSymbolAddress((void**)&total_p, g_total);

    cudaFuncSetAttribute(gcn_fused_kernel<true, true, false>,
                         cudaFuncAttributeMaxDynamicSharedMemorySize, SMEM_BYTES);
    cudaFuncSetAttribute(gcn_fused_kernel<false, false, true>,
                         cudaFuncAttributeMaxDynamicSharedMemorySize, SMEM_BYTES);

    const int T = 256;
    cudaMemsetAsync(cnt_src_p, 0, NN * sizeof(int));
    cudaMemsetAsync(cnt_dst_p, 0, NN * sizeof(int));
    cudaMemsetAsync(total_p, 0, sizeof(int));
    count_deg_kernel<<<(NE / 4 + T - 1) / T, T>>>(src, dst);
    scan_fused_kernel<<<SCAN_B, SCAN_T>>>();     // scan + fill + norms
    fill_csr_kernel<<<(NE / 4 + T - 1) / T, T>>>(src, dst);

    // preconvert all weights (one launch) + x*norm_src -> fp16 h0
    convert_w_all_kernel<<<(4 * FD * FD + T - 1) / T, T>>>(
        Ws[0], Ws[1], Ws[2], Ws[3], wh);
    convert_x_kernel<<<(NN * FD4 + T - 1) / T, T>>>(x, h0);

    const int gemm_blocks = (NN + 63) / 64;
    gcn_fused_kernel<true, true, false><<<gemm_blocks, T, SMEM_BYTES>>>(
        h0, wh + 0 * 128 * SH_STR, bs[0], h1, nullptr, nullptr, nullptr);
    gcn_fused_kernel<true, true, false><<<gemm_blocks, T, SMEM_BYTES>>>(
        h1, wh + 1 * 128 * SH_STR, bs[1], h0, nullptr, nullptr, nullptr);
    gcn_fused_kernel<true, true, false><<<gemm_blocks, T, SMEM_BYTES>>>(
        h0, wh + 2 * 128 * SH_STR, bs[2], h1, nullptr, nullptr, nullptr);
    gcn_fused_kernel<false, false, true><<<gemm_blocks, T, SMEM_BYTES>>>(
        h1, wh + 3 * 128 * SH_STR, bs[3], nullptr, out, gamma, beta);
}